// round 10
// baseline (speedup 1.0000x reference)
#include <cuda_runtime.h>
#include <cstdint>
#include <cstddef>

// Problem constants
#define BATCH 4
#define SEQ   2048
#define EMB   512
#define HEADS 8
#define KDIM  64
#define TOKENS (BATCH * SEQ)          // 8192

// Scratch (allocation-free rule: __device__ globals)
__device__ float g_q  [TOKENS * EMB];   // Q = x @ Wq, [tok, h*64+d]
__device__ float g_ctx[TOKENS * EMB];   // context,    [tok, h*64+d]

// ---------------------------------------------------------------------------
// helpers
// ---------------------------------------------------------------------------
__device__ __forceinline__ uint32_t pack2(float lo, float hi) {
    uint32_t r;
    asm("cvt.rn.bf16x2.f32 %0, %1, %2;" : "=r"(r) : "f"(hi), "f"(lo));
    return r;
}
__device__ __forceinline__ float unlo(uint32_t p) { return __uint_as_float(p << 16); }
__device__ __forceinline__ float unhi(uint32_t p) { return __uint_as_float(p & 0xffff0000u); }
__device__ __forceinline__ uint32_t resid2(float lo, float hi, uint32_t h) {
    return pack2(lo - unlo(h), hi - unhi(h));
}
__device__ __forceinline__ void mma_bf16(float* c,
                                         uint32_t a0, uint32_t a1, uint32_t a2, uint32_t a3,
                                         uint32_t b0, uint32_t b1)
{
    asm volatile(
        "mma.sync.aligned.m16n8k16.row.col.f32.bf16.bf16.f32 "
        "{%0,%1,%2,%3}, {%4,%5,%6,%7}, {%8,%9}, {%0,%1,%2,%3};\n"
        : "+f"(c[0]), "+f"(c[1]), "+f"(c[2]), "+f"(c[3])
        : "r"(a0), "r"(a1), "r"(a2), "r"(a3), "r"(b0), "r"(b1));
}
__device__ __forceinline__ uint32_t smem_u32(const void* p) {
    uint32_t a;
    asm("{ .reg .u64 t; cvta.to.shared.u64 t, %1; cvt.u32.u64 %0, t; }" : "=r"(a) : "l"(p));
    return a;
}
__device__ __forceinline__ void cp16(uint32_t dst, const void* src) {
    asm volatile("cp.async.cg.shared.global [%0], [%1], 16;" :: "r"(dst), "l"(src));
}
#define CP_COMMIT() asm volatile("cp.async.commit_group;" ::: "memory")
#define CP_WAIT0()  asm volatile("cp.async.wait_group 0;" ::: "memory")

// packed smem row widths (uint32 words) — conflict-free fragment LDS
#define KW 36
#define VW 72
#define AW 20

// ===========================================================================
// Split-bf16 GEMM with cp.async single-buffer pipeline: C = A @ B,
// 128x64 tile, BK=32. Ordering makes the single raw buffer race-free:
// convert reads raw -> __syncthreads -> cp writes raw (next tile).
// ===========================================================================
// smem (bytes): Araw [128][36]f32 @0 (18432) | Braw [32][68]f32 @18432 (8704)
//               Ahi @27136 | Alo @37376 | Bhi @47616 | Blo @52224 | end 56832
#define G_ARAW 0
#define G_BRAW 18432
#define G_AHI  27136
#define G_ALO  37376
#define G_BHI  47616
#define G_BLO  52224
#define GEMM_SMEM 56832

__global__ __launch_bounds__(256) void gemm_bf16s(
    const float* __restrict__ A, const float* __restrict__ Bm,
    float* __restrict__ C, int M, int N, int K)
{
    extern __shared__ char smem[];
    float*    araw = (float*)(smem + G_ARAW);
    float*    braw = (float*)(smem + G_BRAW);
    uint32_t* Ahi  = (uint32_t*)(smem + G_AHI);
    uint32_t* Alo  = (uint32_t*)(smem + G_ALO);
    uint32_t* Bhi  = (uint32_t*)(smem + G_BHI);
    uint32_t* Blo  = (uint32_t*)(smem + G_BLO);
    const uint32_t sb = smem_u32(smem);

    const int tid  = threadIdx.x;
    const int warp = tid >> 5, lane = tid & 31;
    const int g = lane >> 2, t = lane & 3;
    const int bn = blockIdx.x << 6;
    const int bm = blockIdx.y << 7;
    const int wm = warp << 4;

    // cp.async mapping
    const int ar  = tid >> 1, ac = (tid & 1) << 4;   // A: row, col base (floats)
    const int br  = tid >> 3, bc = (tid & 7) << 3;   // B: row, col base (floats)
    // convert mapping
    const int cr  = tid >> 1, ccb = (tid & 1) << 4;  // A convert
    const int nn  = (tid & 31) << 1, kk = (tid >> 5) << 2;   // B convert

    float acc[8][4];
#pragma unroll
    for (int n = 0; n < 8; ++n)
#pragma unroll
        for (int i = 0; i < 4; ++i) acc[n][i] = 0.f;

    // prologue: stream tile 0
    {
        const float* as = &A[(size_t)(bm + ar) * K + ac];
        uint32_t ad = sb + G_ARAW + ar * 144 + ac * 4;
#pragma unroll
        for (int i = 0; i < 4; ++i) cp16(ad + 16 * i, as + 4 * i);
        const float* bs = &Bm[(size_t)br * N + bn + bc];
        uint32_t bd = sb + G_BRAW + br * 272 + bc * 4;
#pragma unroll
        for (int i = 0; i < 2; ++i) cp16(bd + 16 * i, bs + 4 * i);
        CP_COMMIT(); CP_WAIT0();
    }
    __syncthreads();

    for (int kt = 0; kt < K; kt += 32) {
        // convert raw(kt) -> packed
        {
            const float* ap = &araw[cr * 36 + ccb];
#pragma unroll
            for (int i = 0; i < 4; ++i) {
                float4 a = *(const float4*)&ap[4 * i];
                uint32_t h0 = pack2(a.x, a.y), h1 = pack2(a.z, a.w);
                int w = cr * AW + (ccb >> 1) + 2 * i;
                *(uint2*)&Ahi[w] = make_uint2(h0, h1);
                *(uint2*)&Alo[w] = make_uint2(resid2(a.x, a.y, h0), resid2(a.z, a.w, h1));
            }
#pragma unroll
            for (int i = 0; i < 2; ++i) {
                int r0 = kk + 2 * i;
                float2 p = *(const float2*)&braw[r0 * 68 + nn];
                float2 q = *(const float2*)&braw[(r0 + 1) * 68 + nn];
                uint32_t h0 = pack2(p.x, q.x), h1 = pack2(p.y, q.y);
                int w = (r0 >> 1) * VW + nn;
                *(uint2*)&Bhi[w] = make_uint2(h0, h1);
                *(uint2*)&Blo[w] = make_uint2(resid2(p.x, q.x, h0), resid2(p.y, q.y, h1));
            }
        }
        __syncthreads();   // raw reads complete before cp overwrites

        // stream tile kt+32 into raw (overlaps compute)
        if (kt + 32 < K) {
            const float* as = &A[(size_t)(bm + ar) * K + kt + 32 + ac];
            uint32_t ad = sb + G_ARAW + ar * 144 + ac * 4;
#pragma unroll
            for (int i = 0; i < 4; ++i) cp16(ad + 16 * i, as + 4 * i);
            const float* bs = &Bm[(size_t)(kt + 32 + br) * N + bn + bc];
            uint32_t bd = sb + G_BRAW + br * 272 + bc * 4;
#pragma unroll
            for (int i = 0; i < 2; ++i) cp16(bd + 16 * i, bs + 4 * i);
            CP_COMMIT();
        }

        // compute on packed tile kt
#pragma unroll
        for (int kc = 0; kc < 2; ++kc) {
            const int wa = (wm + g) * AW + kc * 8 + t;
            uint32_t ah0 = Ahi[wa],     ah1 = Ahi[wa + 8 * AW];
            uint32_t ah2 = Ahi[wa + 4], ah3 = Ahi[wa + 8 * AW + 4];
            uint32_t al0 = Alo[wa],     al1 = Alo[wa + 8 * AW];
            uint32_t al2 = Alo[wa + 4], al3 = Alo[wa + 8 * AW + 4];
#pragma unroll
            for (int n = 0; n < 8; ++n) {
                const int wb = (kc * 8 + t) * VW + n * 8 + g;
                uint32_t bh0 = Bhi[wb], bh1 = Bhi[wb + 4 * VW];
                uint32_t bl0 = Blo[wb], bl1 = Blo[wb + 4 * VW];
                mma_bf16(acc[n], ah0, ah1, ah2, ah3, bh0, bh1);
                mma_bf16(acc[n], al0, al1, al2, al3, bh0, bh1);
                mma_bf16(acc[n], ah0, ah1, ah2, ah3, bl0, bl1);
            }
        }

        if (kt + 32 < K) { CP_WAIT0(); }
        __syncthreads();   // compute reads done + raw landed
    }

    const int row0 = bm + wm + g, row1 = row0 + 8;
#pragma unroll
    for (int n = 0; n < 8; ++n) {
        *(float2*)&C[(size_t)row0 * N + bn + n * 8 + 2 * t] = make_float2(acc[n][0], acc[n][1]);
        *(float2*)&C[(size_t)row1 * N + bn + n * 8 + 2 * t] = make_float2(acc[n][2], acc[n][3]);
    }
}

// ===========================================================================
// Flash attention: round-4 compute core (ONLINE softmax — logits reach +150
// from the correlated Wq mean, fixed max overflows) + cp.async single-buffer
// K/V pipeline (race-free by ordering, same occupancy as round 4).
// 1 CTA = 8 warps per (b, h, 128-query tile); warp owns 16 q rows.
// ===========================================================================
// smem (bytes): Kraw [64][68]f32 @0 (17408) | Vraw @17408 (17408)
//               Khi @34816 | Klo @44032 | Vhi @53248 | Vlo @62464 | end 71680
#define A_KRAW 0
#define A_VRAW 17408
#define A_KHI  34816
#define A_KLO  44032
#define A_VHI  53248
#define A_VLO  62464
#define ATTN_SMEM 71680

__global__ __launch_bounds__(256) void attn_mma(
    const float* __restrict__ Q,   // [tok, 512] from g_q
    const float* __restrict__ Kg,  // [B,H,S,64]
    const float* __restrict__ Vg,  // [B,H,S,64]
    float* __restrict__ Ctx)       // [tok, 512]
{
    extern __shared__ char smem[];
    float*    kraw = (float*)(smem + A_KRAW);
    float*    vraw = (float*)(smem + A_VRAW);
    uint32_t* Khi  = (uint32_t*)(smem + A_KHI);
    uint32_t* Klo  = (uint32_t*)(smem + A_KLO);
    uint32_t* Vhi  = (uint32_t*)(smem + A_VHI);
    uint32_t* Vlo  = (uint32_t*)(smem + A_VLO);
    const uint32_t sb = smem_u32(smem);

    const int tid  = threadIdx.x;
    const int warp = tid >> 5, lane = tid & 31;
    const int gq = lane >> 2, tq = lane & 3;
    const int bh = blockIdx.y;
    const int b  = bh >> 3, h = bh & 7;
    const int q0 = blockIdx.x << 7;
    const int row0 = q0 + warp * 16 + gq;
    const int row1 = row0 + 8;

    const float* kb = Kg + (size_t)bh * SEQ * KDIM;
    const float* vb = Vg + (size_t)bh * SEQ * KDIM;

    // cp.async mapping: row = tid>>2, 16-float chunk base (tid&3)*16
    const int crw = tid >> 2, cch = (tid & 3) << 4;
    // convert mappings (round-4 packed layouts)
    const int lr  = tid >> 2, lc = (tid & 3) << 4;            // K convert
    const int ld2 = (tid & 31) << 1, lrr = (tid >> 5) << 3;   // V convert

    // ---- Q fragments (bf16 hi/lo), pre-scaled by 1/sqrt(64) ----
    uint32_t qh[4][4], ql[4][4];
    {
        const float* qp = Q + (size_t)(b * SEQ) * EMB + h * KDIM;
#pragma unroll
        for (int kc = 0; kc < 4; ++kc) {
            float2 v0 = *(const float2*)&qp[(size_t)row0 * EMB + kc * 16 + 2 * tq];
            float2 v1 = *(const float2*)&qp[(size_t)row1 * EMB + kc * 16 + 2 * tq];
            float2 v2 = *(const float2*)&qp[(size_t)row0 * EMB + kc * 16 + 2 * tq + 8];
            float2 v3 = *(const float2*)&qp[(size_t)row1 * EMB + kc * 16 + 2 * tq + 8];
            v0.x *= 0.125f; v0.y *= 0.125f; v1.x *= 0.125f; v1.y *= 0.125f;
            v2.x *= 0.125f; v2.y *= 0.125f; v3.x *= 0.125f; v3.y *= 0.125f;
            qh[kc][0] = pack2(v0.x, v0.y); ql[kc][0] = resid2(v0.x, v0.y, qh[kc][0]);
            qh[kc][1] = pack2(v1.x, v1.y); ql[kc][1] = resid2(v1.x, v1.y, qh[kc][1]);
            qh[kc][2] = pack2(v2.x, v2.y); ql[kc][2] = resid2(v2.x, v2.y, qh[kc][2]);
            qh[kc][3] = pack2(v3.x, v3.y); ql[kc][3] = resid2(v3.x, v3.y, qh[kc][3]);
        }
    }

    float oacc[8][4];
#pragma unroll
    for (int n = 0; n < 8; ++n)
#pragma unroll
        for (int i = 0; i < 4; ++i) oacc[n][i] = 0.f;
    float m0 = -1e30f, m1 = -1e30f, l0 = 0.f, l1 = 0.f;

    // ---- prologue: stream tile 0 ----
    {
        const float* kp = &kb[(size_t)crw * KDIM + cch];
        const float* vp = &vb[(size_t)crw * KDIM + cch];
        uint32_t kd = sb + A_KRAW + crw * 272 + cch * 4;
        uint32_t vd = sb + A_VRAW + crw * 272 + cch * 4;
#pragma unroll
        for (int i = 0; i < 4; ++i) { cp16(kd + 16 * i, kp + 4 * i); cp16(vd + 16 * i, vp + 4 * i); }
        CP_COMMIT(); CP_WAIT0();
    }
    __syncthreads();

    for (int kt = 0; kt < SEQ / 64; ++kt) {
        // ---- convert raw(kt) -> packed ----
        {
            const float* kp = &kraw[lr * 68 + lc];
#pragma unroll
            for (int i = 0; i < 4; ++i) {
                float4 kv = *(const float4*)&kp[4 * i];
                uint32_t h0 = pack2(kv.x, kv.y), h1 = pack2(kv.z, kv.w);
                int w = lr * KW + (lc >> 1) + 2 * i;
                *(uint2*)&Khi[w] = make_uint2(h0, h1);
                *(uint2*)&Klo[w] = make_uint2(resid2(kv.x, kv.y, h0), resid2(kv.z, kv.w, h1));
            }
#pragma unroll
            for (int i = 0; i < 4; ++i) {
                int r0 = lrr + 2 * i;
                float2 a = *(const float2*)&vraw[r0 * 68 + ld2];
                float2 c = *(const float2*)&vraw[(r0 + 1) * 68 + ld2];
                uint32_t h0 = pack2(a.x, c.x), h1 = pack2(a.y, c.y);
                int w = (r0 >> 1) * VW + ld2;
                *(uint2*)&Vhi[w] = make_uint2(h0, h1);
                *(uint2*)&Vlo[w] = make_uint2(resid2(a.x, c.x, h0), resid2(a.y, c.y, h1));
            }
        }
        __syncthreads();   // raw reads complete before cp overwrites

        // ---- stream tile kt+1 into raw (overlaps compute) ----
        if (kt < SEQ / 64 - 1) {
            const float* kp = &kb[((size_t)((kt + 1) << 6) + crw) * KDIM + cch];
            const float* vp = &vb[((size_t)((kt + 1) << 6) + crw) * KDIM + cch];
            uint32_t kd = sb + A_KRAW + crw * 272 + cch * 4;
            uint32_t vd = sb + A_VRAW + crw * 272 + cch * 4;
#pragma unroll
            for (int i = 0; i < 4; ++i) { cp16(kd + 16 * i, kp + 4 * i); cp16(vd + 16 * i, vp + 4 * i); }
            CP_COMMIT();
        }

        // ---- S = Q K^T (16x64 per warp) ----
        float sacc[8][4];
#pragma unroll
        for (int n = 0; n < 8; ++n)
#pragma unroll
            for (int i = 0; i < 4; ++i) sacc[n][i] = 0.f;

#pragma unroll
        for (int kc = 0; kc < 4; ++kc) {
#pragma unroll
            for (int n = 0; n < 8; ++n) {
                const int wb = (n * 8 + gq) * KW + kc * 8 + tq;
                uint32_t bh0 = Khi[wb], bh1 = Khi[wb + 4];
                uint32_t bl0 = Klo[wb], bl1 = Klo[wb + 4];
                mma_bf16(sacc[n], qh[kc][0], qh[kc][1], qh[kc][2], qh[kc][3], bh0, bh1);
                mma_bf16(sacc[n], ql[kc][0], ql[kc][1], ql[kc][2], ql[kc][3], bh0, bh1);
                mma_bf16(sacc[n], qh[kc][0], qh[kc][1], qh[kc][2], qh[kc][3], bl0, bl1);
            }
        }

        // ---- online softmax (quad-reduce; row0 via c0/c1, row1 via c2/c3) ----
        float tm0 = -1e30f, tm1 = -1e30f;
#pragma unroll
        for (int n = 0; n < 8; ++n) {
            tm0 = fmaxf(tm0, fmaxf(sacc[n][0], sacc[n][1]));
            tm1 = fmaxf(tm1, fmaxf(sacc[n][2], sacc[n][3]));
        }
        tm0 = fmaxf(tm0, __shfl_xor_sync(0xffffffffu, tm0, 1));
        tm0 = fmaxf(tm0, __shfl_xor_sync(0xffffffffu, tm0, 2));
        tm1 = fmaxf(tm1, __shfl_xor_sync(0xffffffffu, tm1, 1));
        tm1 = fmaxf(tm1, __shfl_xor_sync(0xffffffffu, tm1, 2));
        float n0 = fmaxf(m0, tm0), n1 = fmaxf(m1, tm1);
        float sc0 = __expf(m0 - n0), sc1 = __expf(m1 - n1);
        m0 = n0; m1 = n1;
        float ps0 = 0.f, ps1 = 0.f;
#pragma unroll
        for (int n = 0; n < 8; ++n) {
            sacc[n][0] = __expf(sacc[n][0] - n0); ps0 += sacc[n][0];
            sacc[n][1] = __expf(sacc[n][1] - n0); ps0 += sacc[n][1];
            sacc[n][2] = __expf(sacc[n][2] - n1); ps1 += sacc[n][2];
            sacc[n][3] = __expf(sacc[n][3] - n1); ps1 += sacc[n][3];
        }
        ps0 += __shfl_xor_sync(0xffffffffu, ps0, 1);
        ps0 += __shfl_xor_sync(0xffffffffu, ps0, 2);
        ps1 += __shfl_xor_sync(0xffffffffu, ps1, 1);
        ps1 += __shfl_xor_sync(0xffffffffu, ps1, 2);
        l0 = l0 * sc0 + ps0;
        l1 = l1 * sc1 + ps1;
#pragma unroll
        for (int n = 0; n < 8; ++n) {
            oacc[n][0] *= sc0; oacc[n][1] *= sc0;
            oacc[n][2] *= sc1; oacc[n][3] *= sc1;
        }

        // ---- O += P V : accumulator pairs pack directly into A fragments ----
#pragma unroll
        for (int j = 0; j < 4; ++j) {
            uint32_t ph0 = pack2(sacc[2*j][0],   sacc[2*j][1]);
            uint32_t ph1 = pack2(sacc[2*j][2],   sacc[2*j][3]);
            uint32_t ph2 = pack2(sacc[2*j+1][0], sacc[2*j+1][1]);
            uint32_t ph3 = pack2(sacc[2*j+1][2], sacc[2*j+1][3]);
            uint32_t pl0 = resid2(sacc[2*j][0],   sacc[2*j][1],   ph0);
            uint32_t pl1 = resid2(sacc[2*j][2],   sacc[2*j][3],   ph1);
            uint32_t pl2 = resid2(sacc[2*j+1][0], sacc[2*j+1][1], ph2);
            uint32_t pl3 = resid2(sacc[2*j+1][2], sacc[2*j+1][3], ph3);
#pragma unroll
            for (int dt = 0; dt < 8; ++dt) {
                const int wb = (j * 8 + tq) * VW + dt * 8 + gq;
                uint32_t bh0 = Vhi[wb], bh1 = Vhi[wb + 4 * VW];
                uint32_t bl0 = Vlo[wb], bl1 = Vlo[wb + 4 * VW];
                mma_bf16(oacc[dt], ph0, ph1, ph2, ph3, bh0, bh1);
                mma_bf16(oacc[dt], pl0, pl1, pl2, pl3, bh0, bh1);
                mma_bf16(oacc[dt], ph0, ph1, ph2, ph3, bl0, bl1);
            }
        }

        if (kt < SEQ / 64 - 1) { CP_WAIT0(); }
        __syncthreads();   // packed reads done + raw(kt+1) landed
    }

    // ---- normalize + write ctx [tok, h*64+d] ----
    float inv0 = 1.f / l0, inv1 = 1.f / l1;
    float* cp = Ctx + (size_t)(b * SEQ) * EMB + h * KDIM;
#pragma unroll
    for (int dt = 0; dt < 8; ++dt) {
        *(float2*)&cp[(size_t)row0 * EMB + dt * 8 + 2 * tq] =
            make_float2(oacc[dt][0] * inv0, oacc[dt][1] * inv0);
        *(float2*)&cp[(size_t)row1 * EMB + dt * 8 + 2 * tq] =
            make_float2(oacc[dt][2] * inv1, oacc[dt][3] * inv1);
    }
}

// ---------------------------------------------------------------------------
extern "C" void kernel_launch(void* const* d_in, const int* in_sizes, int n_in,
                              void* d_out, int out_size)
{
    const float* x   = (const float*)d_in[0];   // [4,2048,512]
    const float* key = (const float*)d_in[1];   // [4,8,2048,64]
    const float* val = (const float*)d_in[2];   // [4,8,2048,64]
    const float* wq  = (const float*)d_in[3];   // [512,512]
    const float* wo  = (const float*)d_in[4];   // [512,512]
    float* out = (float*)d_out;                 // [4,2048,512]

    float *qptr, *cptr;
    cudaGetSymbolAddress((void**)&qptr, g_q);
    cudaGetSymbolAddress((void**)&cptr, g_ctx);

    cudaFuncSetAttribute(gemm_bf16s, cudaFuncAttributeMaxDynamicSharedMemorySize, GEMM_SMEM);
    cudaFuncSetAttribute(attn_mma,   cudaFuncAttributeMaxDynamicSharedMemorySize, ATTN_SMEM);

    // 1) Q = x @ Wq
    gemm_bf16s<<<dim3(EMB / 64, TOKENS / 128), 256, GEMM_SMEM>>>(x, wq, qptr, TOKENS, EMB, EMB);
    // 2) attention: grid (q-tiles of 128, b*h)
    attn_mma<<<dim3(SEQ / 128, BATCH * HEADS), 256, ATTN_SMEM>>>(qptr, key, val, cptr);
    // 3) out = ctx @ Wo
    gemm_bf16s<<<dim3(EMB / 64, TOKENS / 128), 256, GEMM_SMEM>>>(cptr, wo, out, TOKENS, EMB, EMB);
}

// round 12
// speedup vs baseline: 1.0795x; 1.0795x over previous
#include <cuda_runtime.h>
#include <cstdint>
#include <cstddef>

// Problem constants
#define BATCH 4
#define SEQ   2048
#define EMB   512
#define HEADS 8
#define KDIM  64
#define TOKENS (BATCH * SEQ)          // 8192

// Scratch (allocation-free rule: __device__ globals)
__device__ float g_q  [TOKENS * EMB];   // Q = x @ Wq, [tok, h*64+d]
__device__ float g_ctx[TOKENS * EMB];   // context,    [tok, h*64+d]

// ---------------------------------------------------------------------------
// helpers
// ---------------------------------------------------------------------------
__device__ __forceinline__ uint32_t pack2(float lo, float hi) {
    uint32_t r;
    asm("cvt.rn.bf16x2.f32 %0, %1, %2;" : "=r"(r) : "f"(hi), "f"(lo));
    return r;
}
__device__ __forceinline__ float unlo(uint32_t p) { return __uint_as_float(p << 16); }
__device__ __forceinline__ float unhi(uint32_t p) { return __uint_as_float(p & 0xffff0000u); }
__device__ __forceinline__ uint32_t resid2(float lo, float hi, uint32_t h) {
    return pack2(lo - unlo(h), hi - unhi(h));
}
__device__ __forceinline__ void mma_bf16(float* c,
                                         uint32_t a0, uint32_t a1, uint32_t a2, uint32_t a3,
                                         uint32_t b0, uint32_t b1)
{
    asm volatile(
        "mma.sync.aligned.m16n8k16.row.col.f32.bf16.bf16.f32 "
        "{%0,%1,%2,%3}, {%4,%5,%6,%7}, {%8,%9}, {%0,%1,%2,%3};\n"
        : "+f"(c[0]), "+f"(c[1]), "+f"(c[2]), "+f"(c[3])
        : "r"(a0), "r"(a1), "r"(a2), "r"(a3), "r"(b0), "r"(b1));
}

// packed smem row widths (uint32 words) — conflict-free fragment LDS
#define KW 36   // K/A-style: [row][dpair], 32 pairs + 4 pad
#define VW 72   // V/B-style: [rowpair][col], 64 cols + 8 pad

// ===========================================================================
// Split-bf16 GEMM: C = A @ B, 128x64 tile, BK=64 (8 barrier phases).
// Identical fragment layouts & numerics to the round-4 kernel; only the
// K-extent per load/convert phase doubled.
// ===========================================================================
// smem (bytes): Ahi @0 (18432 = 128*36*4) | Alo @18432
//               Bhi @36864 (9216 = 32*72*4) | Blo @46080 | end 55296
#define G_AHI 0
#define G_ALO 18432
#define G_BHI 36864
#define G_BLO 46080
#define GEMM_SMEM 55296

__global__ __launch_bounds__(256) void gemm_bf16s(
    const float* __restrict__ A, const float* __restrict__ Bm,
    float* __restrict__ C, int M, int N, int K)
{
    extern __shared__ char smem[];
    uint32_t* Ahi = (uint32_t*)(smem + G_AHI);
    uint32_t* Alo = (uint32_t*)(smem + G_ALO);
    uint32_t* Bhi = (uint32_t*)(smem + G_BHI);
    uint32_t* Blo = (uint32_t*)(smem + G_BLO);

    const int tid  = threadIdx.x;
    const int warp = tid >> 5, lane = tid & 31;
    const int g = lane >> 2, t = lane & 3;
    const int bn = blockIdx.x << 6;
    const int bm = blockIdx.y << 7;
    const int wm = warp << 4;

    // converter mappings
    const int cr  = tid >> 1, cc0 = (tid & 1) << 5;          // A: half row (32 cols)
    const int nn  = (tid & 31) << 1, kk = (tid >> 5) << 2;   // B: 2 cols, 4-row group

    float acc[8][4];
#pragma unroll
    for (int n = 0; n < 8; ++n)
#pragma unroll
        for (int i = 0; i < 4; ++i) acc[n][i] = 0.f;

    for (int kt = 0; kt < K; kt += 64) {
        __syncthreads();
        {   // A tile 128x64: thread = half row (32 cols); float4 #i -> words +2i
            const float* ar = &A[(size_t)(bm + cr) * K + kt + cc0];
#pragma unroll
            for (int i = 0; i < 8; ++i) {
                float4 a = *(const float4*)&ar[4 * i];
                uint32_t h0 = pack2(a.x, a.y), h1 = pack2(a.z, a.w);
                int w = cr * KW + (cc0 >> 1) + 2 * i;
                *(uint2*)&Ahi[w] = make_uint2(h0, h1);
                *(uint2*)&Alo[w] = make_uint2(resid2(a.x, a.y, h0), resid2(a.z, a.w, h1));
            }
            // B tile 64x64 -> row-pair layout (two 32-row halves)
#pragma unroll
            for (int half = 0; half < 2; ++half) {
#pragma unroll
                for (int i = 0; i < 2; ++i) {
                    int r0 = 32 * half + kk + 2 * i;
                    float2 p = *(const float2*)&Bm[(size_t)(kt + r0)     * N + bn + nn];
                    float2 q = *(const float2*)&Bm[(size_t)(kt + r0 + 1) * N + bn + nn];
                    uint32_t h0 = pack2(p.x, q.x), h1 = pack2(p.y, q.y);
                    int w = (r0 >> 1) * VW + nn;
                    *(uint2*)&Bhi[w] = make_uint2(h0, h1);
                    *(uint2*)&Blo[w] = make_uint2(resid2(p.x, q.x, h0), resid2(p.y, q.y, h1));
                }
            }
        }
        __syncthreads();

#pragma unroll
        for (int kc = 0; kc < 4; ++kc) {
            const int wa = (wm + g) * KW + kc * 8 + t;
            uint32_t ah0 = Ahi[wa],     ah1 = Ahi[wa + 8 * KW];
            uint32_t ah2 = Ahi[wa + 4], ah3 = Ahi[wa + 8 * KW + 4];
            uint32_t al0 = Alo[wa],     al1 = Alo[wa + 8 * KW];
            uint32_t al2 = Alo[wa + 4], al3 = Alo[wa + 8 * KW + 4];
#pragma unroll
            for (int n = 0; n < 8; ++n) {
                const int wb = (kc * 8 + t) * VW + n * 8 + g;
                uint32_t bh0 = Bhi[wb], bh1 = Bhi[wb + 4 * VW];
                uint32_t bl0 = Blo[wb], bl1 = Blo[wb + 4 * VW];
                mma_bf16(acc[n], ah0, ah1, ah2, ah3, bh0, bh1);
                mma_bf16(acc[n], al0, al1, al2, al3, bh0, bh1);
                mma_bf16(acc[n], ah0, ah1, ah2, ah3, bl0, bl1);
            }
        }
    }

    const int row0 = bm + wm + g, row1 = row0 + 8;
#pragma unroll
    for (int n = 0; n < 8; ++n) {
        *(float2*)&C[(size_t)row0 * N + bn + n * 8 + 2 * t] = make_float2(acc[n][0], acc[n][1]);
        *(float2*)&C[(size_t)row1 * N + bn + n * 8 + 2 * t] = make_float2(acc[n][2], acc[n][3]);
    }
}

// ===========================================================================
// Flash attention: round-4 compute core (ONLINE softmax — logits reach +150
// from the correlated Wq mean, fixed max overflows), 128-key phases:
// one load/convert barrier pair covers TWO round-4-identical 64-key compute
// halves. K converter writes float4 #i to words +2i (round-4 ordering —
// the round-11 bug was a permuted write order here).
// 1 CTA = 8 warps per (b, h, 128-query tile); warp owns 16 q rows.
// ===========================================================================
// smem (bytes): Khi @0 (18432 = 128*36*4) | Klo @18432
//               Vhi @36864 (18432 = 64*72*4) | Vlo @55296 | end 73728
#define A_KHI 0
#define A_KLO 18432
#define A_VHI 36864
#define A_VLO 55296
#define ATTN_SMEM 73728

__global__ __launch_bounds__(256) void attn_mma(
    const float* __restrict__ Q,   // [tok, 512] from g_q
    const float* __restrict__ Kg,  // [B,H,S,64]
    const float* __restrict__ Vg,  // [B,H,S,64]
    float* __restrict__ Ctx)       // [tok, 512]
{
    extern __shared__ char smem[];
    uint32_t* Khi = (uint32_t*)(smem + A_KHI);
    uint32_t* Klo = (uint32_t*)(smem + A_KLO);
    uint32_t* Vhi = (uint32_t*)(smem + A_VHI);
    uint32_t* Vlo = (uint32_t*)(smem + A_VLO);

    const int tid  = threadIdx.x;
    const int warp = tid >> 5, lane = tid & 31;
    const int gq = lane >> 2, tq = lane & 3;
    const int bh = blockIdx.y;
    const int b  = bh >> 3, h = bh & 7;
    const int q0 = blockIdx.x << 7;
    const int row0 = q0 + warp * 16 + gq;
    const int row1 = row0 + 8;

    const float* kb = Kg + (size_t)bh * SEQ * KDIM;
    const float* vb = Vg + (size_t)bh * SEQ * KDIM;

    // converter mappings (round-4 patterns)
    const int lr  = tid >> 2, lc = (tid & 3) << 4;            // K: row, 16-col chunk
    const int ld2 = (tid & 31) << 1, lrr = (tid >> 5) << 3;   // V: col pair, 8-row group

    // ---- Q fragments (bf16 hi/lo), pre-scaled by 1/sqrt(64) ----
    uint32_t qh[4][4], ql[4][4];
    {
        const float* qp = Q + (size_t)(b * SEQ) * EMB + h * KDIM;
#pragma unroll
        for (int kc = 0; kc < 4; ++kc) {
            float2 v0 = *(const float2*)&qp[(size_t)row0 * EMB + kc * 16 + 2 * tq];
            float2 v1 = *(const float2*)&qp[(size_t)row1 * EMB + kc * 16 + 2 * tq];
            float2 v2 = *(const float2*)&qp[(size_t)row0 * EMB + kc * 16 + 2 * tq + 8];
            float2 v3 = *(const float2*)&qp[(size_t)row1 * EMB + kc * 16 + 2 * tq + 8];
            v0.x *= 0.125f; v0.y *= 0.125f; v1.x *= 0.125f; v1.y *= 0.125f;
            v2.x *= 0.125f; v2.y *= 0.125f; v3.x *= 0.125f; v3.y *= 0.125f;
            qh[kc][0] = pack2(v0.x, v0.y); ql[kc][0] = resid2(v0.x, v0.y, qh[kc][0]);
            qh[kc][1] = pack2(v1.x, v1.y); ql[kc][1] = resid2(v1.x, v1.y, qh[kc][1]);
            qh[kc][2] = pack2(v2.x, v2.y); ql[kc][2] = resid2(v2.x, v2.y, qh[kc][2]);
            qh[kc][3] = pack2(v3.x, v3.y); ql[kc][3] = resid2(v3.x, v3.y, qh[kc][3]);
        }
    }

    float oacc[8][4];
#pragma unroll
    for (int n = 0; n < 8; ++n)
#pragma unroll
        for (int i = 0; i < 4; ++i) oacc[n][i] = 0.f;
    float m0 = -1e30f, m1 = -1e30f, l0 = 0.f, l1 = 0.f;

    for (int kt = 0; kt < SEQ / 128; ++kt) {
        __syncthreads();
        {   // ---- load + convert 128 keys of K and V (two 64-row halves) ----
#pragma unroll
            for (int half = 0; half < 2; ++half) {
                // K rows: float4 #i (cols lc+4i..lc+4i+3) -> words w+2i, w+2i+1
                const float* kr = &kb[((size_t)(kt << 7) + half * 64 + lr) * KDIM + lc];
                const int w = (half * 64 + lr) * KW + (lc >> 1);
#pragma unroll
                for (int i = 0; i < 4; ++i) {
                    float4 kv = *(const float4*)&kr[4 * i];
                    uint32_t h0 = pack2(kv.x, kv.y), h1 = pack2(kv.z, kv.w);
                    *(uint2*)&Khi[w + 2 * i] = make_uint2(h0, h1);
                    *(uint2*)&Klo[w + 2 * i] =
                        make_uint2(resid2(kv.x, kv.y, h0), resid2(kv.z, kv.w, h1));
                }
                // V rows
#pragma unroll
                for (int i = 0; i < 4; ++i) {
                    int r0 = lrr + 2 * i;
                    const float* vr = &vb[((size_t)(kt << 7) + half * 64 + r0) * KDIM];
                    float2 a = *(const float2*)&vr[ld2];
                    float2 c = *(const float2*)&vr[KDIM + ld2];
                    uint32_t h0 = pack2(a.x, c.x), h1 = pack2(a.y, c.y);
                    int wv = (half * 32 + (r0 >> 1)) * VW + ld2;
                    *(uint2*)&Vhi[wv] = make_uint2(h0, h1);
                    *(uint2*)&Vlo[wv] = make_uint2(resid2(a.x, c.x, h0), resid2(a.y, c.y, h1));
                }
            }
        }
        __syncthreads();

        // ---- two round-4-identical 64-key compute halves ----
#pragma unroll 1
        for (int half = 0; half < 2; ++half) {
            const int kbase = half * 64 * KW;
            const int vbase = half * 32 * VW;

            // S = Q K^T (16x64 per warp)
            float sacc[8][4];
#pragma unroll
            for (int n = 0; n < 8; ++n)
#pragma unroll
                for (int i = 0; i < 4; ++i) sacc[n][i] = 0.f;

#pragma unroll
            for (int kc = 0; kc < 4; ++kc) {
#pragma unroll
                for (int n = 0; n < 8; ++n) {
                    const int wb = kbase + (n * 8 + gq) * KW + kc * 8 + tq;
                    uint32_t bh0 = Khi[wb], bh1 = Khi[wb + 4];
                    uint32_t bl0 = Klo[wb], bl1 = Klo[wb + 4];
                    mma_bf16(sacc[n], qh[kc][0], qh[kc][1], qh[kc][2], qh[kc][3], bh0, bh1);
                    mma_bf16(sacc[n], ql[kc][0], ql[kc][1], ql[kc][2], ql[kc][3], bh0, bh1);
                    mma_bf16(sacc[n], qh[kc][0], qh[kc][1], qh[kc][2], qh[kc][3], bl0, bl1);
                }
            }

            // online softmax (quad-reduce; row0 via c0/c1, row1 via c2/c3)
            float tm0 = -1e30f, tm1 = -1e30f;
#pragma unroll
            for (int n = 0; n < 8; ++n) {
                tm0 = fmaxf(tm0, fmaxf(sacc[n][0], sacc[n][1]));
                tm1 = fmaxf(tm1, fmaxf(sacc[n][2], sacc[n][3]));
            }
            tm0 = fmaxf(tm0, __shfl_xor_sync(0xffffffffu, tm0, 1));
            tm0 = fmaxf(tm0, __shfl_xor_sync(0xffffffffu, tm0, 2));
            tm1 = fmaxf(tm1, __shfl_xor_sync(0xffffffffu, tm1, 1));
            tm1 = fmaxf(tm1, __shfl_xor_sync(0xffffffffu, tm1, 2));
            float n0 = fmaxf(m0, tm0), n1 = fmaxf(m1, tm1);
            float sc0 = __expf(m0 - n0), sc1 = __expf(m1 - n1);
            m0 = n0; m1 = n1;
            float ps0 = 0.f, ps1 = 0.f;
#pragma unroll
            for (int n = 0; n < 8; ++n) {
                sacc[n][0] = __expf(sacc[n][0] - n0); ps0 += sacc[n][0];
                sacc[n][1] = __expf(sacc[n][1] - n0); ps0 += sacc[n][1];
                sacc[n][2] = __expf(sacc[n][2] - n1); ps1 += sacc[n][2];
                sacc[n][3] = __expf(sacc[n][3] - n1); ps1 += sacc[n][3];
            }
            ps0 += __shfl_xor_sync(0xffffffffu, ps0, 1);
            ps0 += __shfl_xor_sync(0xffffffffu, ps0, 2);
            ps1 += __shfl_xor_sync(0xffffffffu, ps1, 1);
            ps1 += __shfl_xor_sync(0xffffffffu, ps1, 2);
            l0 = l0 * sc0 + ps0;
            l1 = l1 * sc1 + ps1;
#pragma unroll
            for (int n = 0; n < 8; ++n) {
                oacc[n][0] *= sc0; oacc[n][1] *= sc0;
                oacc[n][2] *= sc1; oacc[n][3] *= sc1;
            }

            // O += P V : accumulator pairs pack directly into A fragments
#pragma unroll
            for (int j = 0; j < 4; ++j) {
                uint32_t ph0 = pack2(sacc[2*j][0],   sacc[2*j][1]);
                uint32_t ph1 = pack2(sacc[2*j][2],   sacc[2*j][3]);
                uint32_t ph2 = pack2(sacc[2*j+1][0], sacc[2*j+1][1]);
                uint32_t ph3 = pack2(sacc[2*j+1][2], sacc[2*j+1][3]);
                uint32_t pl0 = resid2(sacc[2*j][0],   sacc[2*j][1],   ph0);
                uint32_t pl1 = resid2(sacc[2*j][2],   sacc[2*j][3],   ph1);
                uint32_t pl2 = resid2(sacc[2*j+1][0], sacc[2*j+1][1], ph2);
                uint32_t pl3 = resid2(sacc[2*j+1][2], sacc[2*j+1][3], ph3);
#pragma unroll
                for (int dt = 0; dt < 8; ++dt) {
                    const int wb = vbase + (j * 8 + tq) * VW + dt * 8 + gq;
                    uint32_t bh0 = Vhi[wb], bh1 = Vhi[wb + 4 * VW];
                    uint32_t bl0 = Vlo[wb], bl1 = Vlo[wb + 4 * VW];
                    mma_bf16(oacc[dt], ph0, ph1, ph2, ph3, bh0, bh1);
                    mma_bf16(oacc[dt], pl0, pl1, pl2, pl3, bh0, bh1);
                    mma_bf16(oacc[dt], ph0, ph1, ph2, ph3, bl0, bl1);
                }
            }
        }
    }

    // ---- normalize + write ctx [tok, h*64+d] ----
    float inv0 = 1.f / l0, inv1 = 1.f / l1;
    float* cp = Ctx + (size_t)(b * SEQ) * EMB + h * KDIM;
#pragma unroll
    for (int dt = 0; dt < 8; ++dt) {
        *(float2*)&cp[(size_t)row0 * EMB + dt * 8 + 2 * tq] =
            make_float2(oacc[dt][0] * inv0, oacc[dt][1] * inv0);
        *(float2*)&cp[(size_t)row1 * EMB + dt * 8 + 2 * tq] =
            make_float2(oacc[dt][2] * inv1, oacc[dt][3] * inv1);
    }
}

// ---------------------------------------------------------------------------
extern "C" void kernel_launch(void* const* d_in, const int* in_sizes, int n_in,
                              void* d_out, int out_size)
{
    const float* x   = (const float*)d_in[0];   // [4,2048,512]
    const float* key = (const float*)d_in[1];   // [4,8,2048,64]
    const float* val = (const float*)d_in[2];   // [4,8,2048,64]
    const float* wq  = (const float*)d_in[3];   // [512,512]
    const float* wo  = (const float*)d_in[4];   // [512,512]
    float* out = (float*)d_out;                 // [4,2048,512]

    float *qptr, *cptr;
    cudaGetSymbolAddress((void**)&qptr, g_q);
    cudaGetSymbolAddress((void**)&cptr, g_ctx);

    cudaFuncSetAttribute(gemm_bf16s, cudaFuncAttributeMaxDynamicSharedMemorySize, GEMM_SMEM);
    cudaFuncSetAttribute(attn_mma,   cudaFuncAttributeMaxDynamicSharedMemorySize, ATTN_SMEM);

    // 1) Q = x @ Wq
    gemm_bf16s<<<dim3(EMB / 64, TOKENS / 128), 256, GEMM_SMEM>>>(x, wq, qptr, TOKENS, EMB, EMB);
    // 2) attention: grid (q-tiles of 128, b*h)
    attn_mma<<<dim3(SEQ / 128, BATCH * HEADS), 256, ATTN_SMEM>>>(qptr, key, val, cptr);
    // 3) out = ctx @ Wo
    gemm_bf16s<<<dim3(EMB / 64, TOKENS / 128), 256, GEMM_SMEM>>>(cptr, wo, out, TOKENS, EMB, EMB);
}

// round 13
// speedup vs baseline: 1.1574x; 1.0721x over previous
#include <cuda_runtime.h>
#include <cstdint>
#include <cstddef>

// Problem constants
#define BATCH 4
#define SEQ   2048
#define EMB   512
#define HEADS 8
#define KDIM  64
#define TOKENS (BATCH * SEQ)          // 8192

// Scratch (allocation-free rule: __device__ globals)
__device__ float g_q  [TOKENS * EMB];   // Q = x @ Wq, [tok, h*64+d]
__device__ float g_ctx[TOKENS * EMB];   // context,    [tok, h*64+d]

// ---------------------------------------------------------------------------
// helpers
// ---------------------------------------------------------------------------
__device__ __forceinline__ uint32_t pack2(float lo, float hi) {
    uint32_t r;
    asm("cvt.rn.bf16x2.f32 %0, %1, %2;" : "=r"(r) : "f"(hi), "f"(lo));
    return r;
}
__device__ __forceinline__ float unlo(uint32_t p) { return __uint_as_float(p << 16); }
__device__ __forceinline__ float unhi(uint32_t p) { return __uint_as_float(p & 0xffff0000u); }
__device__ __forceinline__ uint32_t resid2(float lo, float hi, uint32_t h) {
    return pack2(lo - unlo(h), hi - unhi(h));
}
__device__ __forceinline__ void mma_bf16(float* c,
                                         uint32_t a0, uint32_t a1, uint32_t a2, uint32_t a3,
                                         uint32_t b0, uint32_t b1)
{
    asm volatile(
        "mma.sync.aligned.m16n8k16.row.col.f32.bf16.bf16.f32 "
        "{%0,%1,%2,%3}, {%4,%5,%6,%7}, {%8,%9}, {%0,%1,%2,%3};\n"
        : "+f"(c[0]), "+f"(c[1]), "+f"(c[2]), "+f"(c[3])
        : "r"(a0), "r"(a1), "r"(a2), "r"(a3), "r"(b0), "r"(b1));
}

// packed smem row widths (uint32 words) — conflict-free fragment LDS
#define KW  36   // K/A-style: [row][dpair], 32 pairs + 4 pad
#define VW  72   // V-style: [rowpair][col], 64 cols + 8 pad
#define VW2 136  // B-style (128-wide): [rowpair][col], 128 cols + 8 pad
#define AW  20   // A packed row width

// ===========================================================================
// Split-bf16 GEMM: C = A @ B, 128x128 tile, BK=32. Grid 256 CTAs -> one
// wave at 2 CTAs/SM (wave efficiency ~100% vs 58% for the 512-CTA config).
// Per-output summation order identical to the round-4 kernel.
// ===========================================================================
__global__ __launch_bounds__(256) void gemm_bf16s(
    const float* __restrict__ A, const float* __restrict__ Bm,
    float* __restrict__ C, int M, int N, int K)
{
    __shared__ uint32_t Ahi[128 * AW], Alo[128 * AW];
    __shared__ uint32_t Bhi[16 * VW2], Blo[16 * VW2];

    const int tid  = threadIdx.x;
    const int warp = tid >> 5, lane = tid & 31;
    const int g = lane >> 2, t = lane & 3;
    const int bn = blockIdx.x << 7;     // 128-wide N tile
    const int bm = blockIdx.y << 7;
    const int wm = warp << 4;

    // converter mappings
    const int cr = tid >> 1, c16 = (tid & 1) << 4;        // A: half row (16 cols)
    const int nn = (tid & 63) << 1, rr = (tid >> 6) << 3; // B: col pair, 8-row group

    float acc[16][4];
#pragma unroll
    for (int n = 0; n < 16; ++n)
#pragma unroll
        for (int i = 0; i < 4; ++i) acc[n][i] = 0.f;

    for (int kt = 0; kt < K; kt += 32) {
        __syncthreads();
        {   // A tile 128x32: thread = half row; float4 #i -> words +2i
            const float* ar = &A[(size_t)(bm + cr) * K + kt + c16];
#pragma unroll
            for (int i = 0; i < 4; ++i) {
                float4 a = *(const float4*)&ar[4 * i];
                uint32_t h0 = pack2(a.x, a.y), h1 = pack2(a.z, a.w);
                int w = cr * AW + (c16 >> 1) + 2 * i;
                *(uint2*)&Ahi[w] = make_uint2(h0, h1);
                *(uint2*)&Alo[w] = make_uint2(resid2(a.x, a.y, h0), resid2(a.z, a.w, h1));
            }
            // B tile 32x128 -> row-pair layout: thread = 2 cols x 4 rowpairs
#pragma unroll
            for (int i = 0; i < 4; ++i) {
                int r0 = rr + 2 * i;
                float2 p = *(const float2*)&Bm[(size_t)(kt + r0)     * N + bn + nn];
                float2 q = *(const float2*)&Bm[(size_t)(kt + r0 + 1) * N + bn + nn];
                uint32_t h0 = pack2(p.x, q.x), h1 = pack2(p.y, q.y);
                int w = (r0 >> 1) * VW2 + nn;
                *(uint2*)&Bhi[w] = make_uint2(h0, h1);
                *(uint2*)&Blo[w] = make_uint2(resid2(p.x, q.x, h0), resid2(p.y, q.y, h1));
            }
        }
        __syncthreads();

#pragma unroll
        for (int kc = 0; kc < 2; ++kc) {
            const int wa = (wm + g) * AW + kc * 8 + t;
            uint32_t ah0 = Ahi[wa],     ah1 = Ahi[wa + 8 * AW];
            uint32_t ah2 = Ahi[wa + 4], ah3 = Ahi[wa + 8 * AW + 4];
            uint32_t al0 = Alo[wa],     al1 = Alo[wa + 8 * AW];
            uint32_t al2 = Alo[wa + 4], al3 = Alo[wa + 8 * AW + 4];
#pragma unroll
            for (int n = 0; n < 16; ++n) {
                const int wb = (kc * 8 + t) * VW2 + n * 8 + g;
                uint32_t bh0 = Bhi[wb], bh1 = Bhi[wb + 4 * VW2];
                uint32_t bl0 = Blo[wb], bl1 = Blo[wb + 4 * VW2];
                mma_bf16(acc[n], ah0, ah1, ah2, ah3, bh0, bh1);
                mma_bf16(acc[n], al0, al1, al2, al3, bh0, bh1);
                mma_bf16(acc[n], ah0, ah1, ah2, ah3, bl0, bl1);
            }
        }
    }

    const int row0 = bm + wm + g, row1 = row0 + 8;
#pragma unroll
    for (int n = 0; n < 16; ++n) {
        *(float2*)&C[(size_t)row0 * N + bn + n * 8 + 2 * t] = make_float2(acc[n][0], acc[n][1]);
        *(float2*)&C[(size_t)row1 * N + bn + n * 8 + 2 * t] = make_float2(acc[n][2], acc[n][3]);
    }
}

// ===========================================================================
// Flash attention (round-4 kernel VERBATIM — the proven 422us core):
// split-bf16 mma.sync, online softmax, static smem, no cp.async.
// 1 CTA = 8 warps per (b, h, 128-query tile); warp owns 16 q rows.
// ===========================================================================
__global__ __launch_bounds__(256) void attn_mma(
    const float* __restrict__ Q,   // [tok, 512] from g_q
    const float* __restrict__ Kg,  // [B,H,S,64]
    const float* __restrict__ Vg,  // [B,H,S,64]
    float* __restrict__ Ctx)       // [tok, 512]
{
    __shared__ uint32_t Khi[64 * KW], Klo[64 * KW];   // [key][dpair]
    __shared__ uint32_t Vhi[32 * VW], Vlo[32 * VW];   // [rowpair][d]

    const int tid  = threadIdx.x;
    const int warp = tid >> 5, lane = tid & 31;
    const int gq = lane >> 2, tq = lane & 3;
    const int bh = blockIdx.y;
    const int b  = bh >> 3, h = bh & 7;
    const int q0 = blockIdx.x << 7;
    const int row0 = q0 + warp * 16 + gq;
    const int row1 = row0 + 8;

    const float* kb = Kg + (size_t)bh * SEQ * KDIM;
    const float* vb = Vg + (size_t)bh * SEQ * KDIM;

    // loader indices
    const int lr  = tid >> 2, lc = (tid & 3) << 4;            // K: row, 16-col chunk
    const int ld2 = (tid & 31) << 1, lrr = (tid >> 5) << 3;   // V: col pair, 8-row group

    // ---- Q fragments (bf16 hi/lo), pre-scaled by 1/sqrt(64) ----
    uint32_t qh[4][4], ql[4][4];
    {
        const float* qp = Q + (size_t)(b * SEQ) * EMB + h * KDIM;
#pragma unroll
        for (int kc = 0; kc < 4; ++kc) {
            float2 v0 = *(const float2*)&qp[(size_t)row0 * EMB + kc * 16 + 2 * tq];
            float2 v1 = *(const float2*)&qp[(size_t)row1 * EMB + kc * 16 + 2 * tq];
            float2 v2 = *(const float2*)&qp[(size_t)row0 * EMB + kc * 16 + 2 * tq + 8];
            float2 v3 = *(const float2*)&qp[(size_t)row1 * EMB + kc * 16 + 2 * tq + 8];
            v0.x *= 0.125f; v0.y *= 0.125f; v1.x *= 0.125f; v1.y *= 0.125f;
            v2.x *= 0.125f; v2.y *= 0.125f; v3.x *= 0.125f; v3.y *= 0.125f;
            qh[kc][0] = pack2(v0.x, v0.y); ql[kc][0] = resid2(v0.x, v0.y, qh[kc][0]);
            qh[kc][1] = pack2(v1.x, v1.y); ql[kc][1] = resid2(v1.x, v1.y, qh[kc][1]);
            qh[kc][2] = pack2(v2.x, v2.y); ql[kc][2] = resid2(v2.x, v2.y, qh[kc][2]);
            qh[kc][3] = pack2(v3.x, v3.y); ql[kc][3] = resid2(v3.x, v3.y, qh[kc][3]);
        }
    }

    float oacc[8][4];
#pragma unroll
    for (int n = 0; n < 8; ++n)
#pragma unroll
        for (int i = 0; i < 4; ++i) oacc[n][i] = 0.f;
    float m0 = -1e30f, m1 = -1e30f, l0 = 0.f, l1 = 0.f;

    for (int kt = 0; kt < SEQ / 64; ++kt) {
        __syncthreads();
        {   // K tile 64x64 -> Khi/Klo [key][dpair]
            const float* kr = &kb[((size_t)(kt << 6) + lr) * KDIM + lc];
#pragma unroll
            for (int i = 0; i < 4; ++i) {
                float4 kv = *(const float4*)&kr[4 * i];
                uint32_t h0 = pack2(kv.x, kv.y), h1 = pack2(kv.z, kv.w);
                int w = lr * KW + (lc >> 1) + 2 * i;
                *(uint2*)&Khi[w] = make_uint2(h0, h1);
                *(uint2*)&Klo[w] = make_uint2(resid2(kv.x, kv.y, h0), resid2(kv.z, kv.w, h1));
            }
            // V tile 64x64 -> Vhi/Vlo [rowpair][d]
#pragma unroll
            for (int i = 0; i < 4; ++i) {
                int r0 = lrr + 2 * i;
                float2 a = *(const float2*)&vb[((size_t)(kt << 6) + r0)     * KDIM + ld2];
                float2 c = *(const float2*)&vb[((size_t)(kt << 6) + r0 + 1) * KDIM + ld2];
                uint32_t h0 = pack2(a.x, c.x), h1 = pack2(a.y, c.y);
                int w = (r0 >> 1) * VW + ld2;
                *(uint2*)&Vhi[w] = make_uint2(h0, h1);
                *(uint2*)&Vlo[w] = make_uint2(resid2(a.x, c.x, h0), resid2(a.y, c.y, h1));
            }
        }
        __syncthreads();

        // ---- S = Q K^T (16x64 per warp) ----
        float sacc[8][4];
#pragma unroll
        for (int n = 0; n < 8; ++n)
#pragma unroll
            for (int i = 0; i < 4; ++i) sacc[n][i] = 0.f;

#pragma unroll
        for (int kc = 0; kc < 4; ++kc) {
#pragma unroll
            for (int n = 0; n < 8; ++n) {
                const int wb = (n * 8 + gq) * KW + kc * 8 + tq;
                uint32_t bh0 = Khi[wb], bh1 = Khi[wb + 4];
                uint32_t bl0 = Klo[wb], bl1 = Klo[wb + 4];
                mma_bf16(sacc[n], qh[kc][0], qh[kc][1], qh[kc][2], qh[kc][3], bh0, bh1);
                mma_bf16(sacc[n], ql[kc][0], ql[kc][1], ql[kc][2], ql[kc][3], bh0, bh1);
                mma_bf16(sacc[n], qh[kc][0], qh[kc][1], qh[kc][2], qh[kc][3], bl0, bl1);
            }
        }

        // ---- online softmax (quad-reduce; row0 via c0/c1, row1 via c2/c3) ----
        float tm0 = -1e30f, tm1 = -1e30f;
#pragma unroll
        for (int n = 0; n < 8; ++n) {
            tm0 = fmaxf(tm0, fmaxf(sacc[n][0], sacc[n][1]));
            tm1 = fmaxf(tm1, fmaxf(sacc[n][2], sacc[n][3]));
        }
        tm0 = fmaxf(tm0, __shfl_xor_sync(0xffffffffu, tm0, 1));
        tm0 = fmaxf(tm0, __shfl_xor_sync(0xffffffffu, tm0, 2));
        tm1 = fmaxf(tm1, __shfl_xor_sync(0xffffffffu, tm1, 1));
        tm1 = fmaxf(tm1, __shfl_xor_sync(0xffffffffu, tm1, 2));
        float n0 = fmaxf(m0, tm0), n1 = fmaxf(m1, tm1);
        float sc0 = __expf(m0 - n0), sc1 = __expf(m1 - n1);
        m0 = n0; m1 = n1;
        float ps0 = 0.f, ps1 = 0.f;
#pragma unroll
        for (int n = 0; n < 8; ++n) {
            sacc[n][0] = __expf(sacc[n][0] - n0); ps0 += sacc[n][0];
            sacc[n][1] = __expf(sacc[n][1] - n0); ps0 += sacc[n][1];
            sacc[n][2] = __expf(sacc[n][2] - n1); ps1 += sacc[n][2];
            sacc[n][3] = __expf(sacc[n][3] - n1); ps1 += sacc[n][3];
        }
        ps0 += __shfl_xor_sync(0xffffffffu, ps0, 1);
        ps0 += __shfl_xor_sync(0xffffffffu, ps0, 2);
        ps1 += __shfl_xor_sync(0xffffffffu, ps1, 1);
        ps1 += __shfl_xor_sync(0xffffffffu, ps1, 2);
        l0 = l0 * sc0 + ps0;
        l1 = l1 * sc1 + ps1;
#pragma unroll
        for (int n = 0; n < 8; ++n) {
            oacc[n][0] *= sc0; oacc[n][1] *= sc0;
            oacc[n][2] *= sc1; oacc[n][3] *= sc1;
        }

        // ---- O += P V : accumulator pairs pack directly into A fragments ----
#pragma unroll
        for (int j = 0; j < 4; ++j) {
            uint32_t ph0 = pack2(sacc[2*j][0],   sacc[2*j][1]);
            uint32_t ph1 = pack2(sacc[2*j][2],   sacc[2*j][3]);
            uint32_t ph2 = pack2(sacc[2*j+1][0], sacc[2*j+1][1]);
            uint32_t ph3 = pack2(sacc[2*j+1][2], sacc[2*j+1][3]);
            uint32_t pl0 = resid2(sacc[2*j][0],   sacc[2*j][1],   ph0);
            uint32_t pl1 = resid2(sacc[2*j][2],   sacc[2*j][3],   ph1);
            uint32_t pl2 = resid2(sacc[2*j+1][0], sacc[2*j+1][1], ph2);
            uint32_t pl3 = resid2(sacc[2*j+1][2], sacc[2*j+1][3], ph3);
#pragma unroll
            for (int dt = 0; dt < 8; ++dt) {
                const int wb = (j * 8 + tq) * VW + dt * 8 + gq;
                uint32_t bh0 = Vhi[wb], bh1 = Vhi[wb + 4 * VW];
                uint32_t bl0 = Vlo[wb], bl1 = Vlo[wb + 4 * VW];
                mma_bf16(oacc[dt], ph0, ph1, ph2, ph3, bh0, bh1);
                mma_bf16(oacc[dt], pl0, pl1, pl2, pl3, bh0, bh1);
                mma_bf16(oacc[dt], ph0, ph1, ph2, ph3, bl0, bl1);
            }
        }
    }

    // ---- normalize + write ctx [tok, h*64+d] ----
    float inv0 = 1.f / l0, inv1 = 1.f / l1;
    float* cp = Ctx + (size_t)(b * SEQ) * EMB + h * KDIM;
#pragma unroll
    for (int dt = 0; dt < 8; ++dt) {
        *(float2*)&cp[(size_t)row0 * EMB + dt * 8 + 2 * tq] =
            make_float2(oacc[dt][0] * inv0, oacc[dt][1] * inv0);
        *(float2*)&cp[(size_t)row1 * EMB + dt * 8 + 2 * tq] =
            make_float2(oacc[dt][2] * inv1, oacc[dt][3] * inv1);
    }
}

// ---------------------------------------------------------------------------
extern "C" void kernel_launch(void* const* d_in, const int* in_sizes, int n_in,
                              void* d_out, int out_size)
{
    const float* x   = (const float*)d_in[0];   // [4,2048,512]
    const float* key = (const float*)d_in[1];   // [4,8,2048,64]
    const float* val = (const float*)d_in[2];   // [4,8,2048,64]
    const float* wq  = (const float*)d_in[3];   // [512,512]
    const float* wo  = (const float*)d_in[4];   // [512,512]
    float* out = (float*)d_out;                 // [4,2048,512]

    float *qptr, *cptr;
    cudaGetSymbolAddress((void**)&qptr, g_q);
    cudaGetSymbolAddress((void**)&cptr, g_ctx);

    // 1) Q = x @ Wq   : grid (512/128, 8192/128) = (4, 64) = 256 CTAs
    gemm_bf16s<<<dim3(EMB / 128, TOKENS / 128), 256>>>(x, wq, qptr, TOKENS, EMB, EMB);
    // 2) attention    : grid (q-tiles of 128, b*h)
    attn_mma<<<dim3(SEQ / 128, BATCH * HEADS), 256>>>(qptr, key, val, cptr);
    // 3) out = ctx @ Wo
    gemm_bf16s<<<dim3(EMB / 128, TOKENS / 128), 256>>>(cptr, wo, out, TOKENS, EMB, EMB);
}

// round 15
// speedup vs baseline: 1.2410x; 1.0722x over previous
#include <cuda_runtime.h>
#include <cstdint>
#include <cstddef>

// Problem constants
#define BATCH 4
#define SEQ   2048
#define EMB   512
#define HEADS 8
#define KDIM  64
#define TOKENS (BATCH * SEQ)          // 8192
#define BH    (BATCH * HEADS)         // 32

// Scratch (allocation-free rule: __device__ globals)
__device__ float    g_q  [TOKENS * EMB];   // Q = x @ Wq, [tok, h*64+d]
__device__ float    g_ctx[TOKENS * EMB];   // context,    [tok, h*64+d]
__device__ uint32_t g_kp_hi[BH * SEQ * 32], g_kp_lo[BH * SEQ * 32];   // K dpairs
__device__ uint32_t g_vp_hi[BH * 1024 * 64], g_vp_lo[BH * 1024 * 64]; // V rowpairs

// ---------------------------------------------------------------------------
// helpers
// ---------------------------------------------------------------------------
__device__ __forceinline__ uint32_t pack2(float lo, float hi) {
    uint32_t r;
    asm("cvt.rn.bf16x2.f32 %0, %1, %2;" : "=r"(r) : "f"(hi), "f"(lo));
    return r;
}
__device__ __forceinline__ float unlo(uint32_t p) { return __uint_as_float(p << 16); }
__device__ __forceinline__ float unhi(uint32_t p) { return __uint_as_float(p & 0xffff0000u); }
__device__ __forceinline__ uint32_t resid2(float lo, float hi, uint32_t h) {
    return pack2(lo - unlo(h), hi - unhi(h));
}
__device__ __forceinline__ void mma_bf16(float* c,
                                         uint32_t a0, uint32_t a1, uint32_t a2, uint32_t a3,
                                         uint32_t b0, uint32_t b1)
{
    asm volatile(
        "mma.sync.aligned.m16n8k16.row.col.f32.bf16.bf16.f32 "
        "{%0,%1,%2,%3}, {%4,%5,%6,%7}, {%8,%9}, {%0,%1,%2,%3};\n"
        : "+f"(c[0]), "+f"(c[1]), "+f"(c[2]), "+f"(c[3])
        : "r"(a0), "r"(a1), "r"(a2), "r"(a3), "r"(b0), "r"(b1));
}

// smem row widths (uint32 words) — conflict-free fragment LDS (r4/r13 proven)
#define KW  36   // K/A-style: [row][pair], 32 pairs + 4 pad
#define VW  72   // V-style: [rowpair][col], 64 cols + 8 pad
#define VW2 136  // B-style (128-wide): [rowpair][col], 128 cols + 8 pad
#define AW  20   // A packed row width

// ===========================================================================
// Pre-pack kernels (one-time, memory-bound).
// pack_cont: pairs along contiguous dim — hi word i = pack2(src[2i], src[2i+1])
// pack_rows: pairs of rows (stride W) — hi[rp*W+d] = pack2(src[2rp*W+d], src[(2rp+1)*W+d])
// Both put the EVEN element in the low bf16 half (matches in-kernel convert).
// ===========================================================================
__global__ void pack_cont(const float* __restrict__ src,
                          uint32_t* __restrict__ hi, uint32_t* __restrict__ lo, int n4)
{
    int i = blockIdx.x * blockDim.x + threadIdx.x;
    if (i >= n4) return;
    float4 a = ((const float4*)src)[i];
    uint32_t h0 = pack2(a.x, a.y), h1 = pack2(a.z, a.w);
    ((uint2*)hi)[i] = make_uint2(h0, h1);
    ((uint2*)lo)[i] = make_uint2(resid2(a.x, a.y, h0), resid2(a.z, a.w, h1));
}
__global__ void pack_rows(const float* __restrict__ src,
                          uint32_t* __restrict__ hi, uint32_t* __restrict__ lo,
                          int npairs2, int W)
{
    int j = blockIdx.x * blockDim.x + threadIdx.x;
    if (j >= npairs2) return;
    int i2 = 2 * j;
    int rp = i2 / W, d = i2 % W;
    float2 r0 = *(const float2*)&src[(size_t)(2 * rp) * W + d];
    float2 r1 = *(const float2*)&src[(size_t)(2 * rp + 1) * W + d];
    uint32_t h0 = pack2(r0.x, r1.x), h1 = pack2(r0.y, r1.y);
    *(uint2*)&hi[i2] = make_uint2(h0, h1);
    *(uint2*)&lo[i2] = make_uint2(resid2(r0.x, r1.x, h0), resid2(r0.y, r1.y, h1));
}

// ===========================================================================
// Split-bf16 GEMM (round-13 VERBATIM): C = A @ B, 128x128 tile, BK=32,
// single-wave grid (256 CTAs at 2 CTAs/SM).
// ===========================================================================
__global__ __launch_bounds__(256) void gemm_bf16s(
    const float* __restrict__ A, const float* __restrict__ Bm,
    float* __restrict__ C, int M, int N, int K)
{
    __shared__ uint32_t Ahi[128 * AW], Alo[128 * AW];
    __shared__ uint32_t Bhi[16 * VW2], Blo[16 * VW2];

    const int tid  = threadIdx.x;
    const int warp = tid >> 5, lane = tid & 31;
    const int g = lane >> 2, t = lane & 3;
    const int bn = blockIdx.x << 7;
    const int bm = blockIdx.y << 7;
    const int wm = warp << 4;

    const int cr = tid >> 1, c16 = (tid & 1) << 4;
    const int nn = (tid & 63) << 1, rr = (tid >> 6) << 3;

    float acc[16][4];
#pragma unroll
    for (int n = 0; n < 16; ++n)
#pragma unroll
        for (int i = 0; i < 4; ++i) acc[n][i] = 0.f;

    for (int kt = 0; kt < K; kt += 32) {
        __syncthreads();
        {
            const float* ar = &A[(size_t)(bm + cr) * K + kt + c16];
#pragma unroll
            for (int i = 0; i < 4; ++i) {
                float4 a = *(const float4*)&ar[4 * i];
                uint32_t h0 = pack2(a.x, a.y), h1 = pack2(a.z, a.w);
                int w = cr * AW + (c16 >> 1) + 2 * i;
                *(uint2*)&Ahi[w] = make_uint2(h0, h1);
                *(uint2*)&Alo[w] = make_uint2(resid2(a.x, a.y, h0), resid2(a.z, a.w, h1));
            }
#pragma unroll
            for (int i = 0; i < 4; ++i) {
                int r0 = rr + 2 * i;
                float2 p = *(const float2*)&Bm[(size_t)(kt + r0)     * N + bn + nn];
                float2 q = *(const float2*)&Bm[(size_t)(kt + r0 + 1) * N + bn + nn];
                uint32_t h0 = pack2(p.x, q.x), h1 = pack2(p.y, q.y);
                int w = (r0 >> 1) * VW2 + nn;
                *(uint2*)&Bhi[w] = make_uint2(h0, h1);
                *(uint2*)&Blo[w] = make_uint2(resid2(p.x, q.x, h0), resid2(p.y, q.y, h1));
            }
        }
        __syncthreads();

#pragma unroll
        for (int kc = 0; kc < 2; ++kc) {
            const int wa = (wm + g) * AW + kc * 8 + t;
            uint32_t ah0 = Ahi[wa],     ah1 = Ahi[wa + 8 * AW];
            uint32_t ah2 = Ahi[wa + 4], ah3 = Ahi[wa + 8 * AW + 4];
            uint32_t al0 = Alo[wa],     al1 = Alo[wa + 8 * AW];
            uint32_t al2 = Alo[wa + 4], al3 = Alo[wa + 8 * AW + 4];
#pragma unroll
            for (int n = 0; n < 16; ++n) {
                const int wb = (kc * 8 + t) * VW2 + n * 8 + g;
                uint32_t bh0 = Bhi[wb], bh1 = Bhi[wb + 4 * VW2];
                uint32_t bl0 = Blo[wb], bl1 = Blo[wb + 4 * VW2];
                mma_bf16(acc[n], ah0, ah1, ah2, ah3, bh0, bh1);
                mma_bf16(acc[n], al0, al1, al2, al3, bh0, bh1);
                mma_bf16(acc[n], ah0, ah1, ah2, ah3, bl0, bl1);
            }
        }
    }

    const int row0 = bm + wm + g, row1 = row0 + 8;
#pragma unroll
    for (int n = 0; n < 16; ++n) {
        *(float2*)&C[(size_t)row0 * N + bn + n * 8 + 2 * t] = make_float2(acc[n][0], acc[n][1]);
        *(float2*)&C[(size_t)row1 * N + bn + n * 8 + 2 * t] = make_float2(acc[n][2], acc[n][3]);
    }
}

// ===========================================================================
// Flash attention: round-4 compute core VERBATIM (online softmax, fp32 ctx
// epilogue); K/V tiles filled from pre-packed planes — pure LDG.128->STS.128,
// zero conversion instructions in the mainloop.
// 1 CTA = 8 warps per (b, h, 128-query tile); warp owns 16 q rows.
// ===========================================================================
__global__ __launch_bounds__(256) void attn_mma(
    const float* __restrict__ Q,          // [tok, 512] fp32 from g_q
    const uint32_t* __restrict__ Khig, const uint32_t* __restrict__ Klog,
    const uint32_t* __restrict__ Vhig, const uint32_t* __restrict__ Vlog,
    float* __restrict__ Ctx)              // [tok, 512] fp32
{
    __shared__ uint32_t Khi[64 * KW], Klo[64 * KW];   // [key][dpair]
    __shared__ uint32_t Vhi[32 * VW], Vlo[32 * VW];   // [rowpair][d]

    const int tid  = threadIdx.x;
    const int warp = tid >> 5, lane = tid & 31;
    const int gq = lane >> 2, tq = lane & 3;
    const int bh = blockIdx.y;
    const int b  = bh >> 3, h = bh & 7;
    const int q0 = blockIdx.x << 7;
    const int row0 = q0 + warp * 16 + gq;
    const int row1 = row0 + 8;

    const uint32_t* khb = Khig + (size_t)bh * SEQ * 32;
    const uint32_t* klb = Klog + (size_t)bh * SEQ * 32;
    const uint32_t* vhb = Vhig + (size_t)bh * 1024 * 64;
    const uint32_t* vlb = Vlog + (size_t)bh * 1024 * 64;

    // fill mappings (pure copy)
    const int fk = tid >> 2, fkp = (tid & 3) << 3;    // K: key, dpair base
    const int fv = tid >> 3, fvd = (tid & 7) << 3;    // V: rowpair, dim base

    // ---- Q fragments (bf16 hi/lo), pre-scaled by 1/sqrt(64) ----
    uint32_t qh[4][4], ql[4][4];
    {
        const float* qp = Q + (size_t)(b * SEQ) * EMB + h * KDIM;
#pragma unroll
        for (int kc = 0; kc < 4; ++kc) {
            float2 v0 = *(const float2*)&qp[(size_t)row0 * EMB + kc * 16 + 2 * tq];
            float2 v1 = *(const float2*)&qp[(size_t)row1 * EMB + kc * 16 + 2 * tq];
            float2 v2 = *(const float2*)&qp[(size_t)row0 * EMB + kc * 16 + 2 * tq + 8];
            float2 v3 = *(const float2*)&qp[(size_t)row1 * EMB + kc * 16 + 2 * tq + 8];
            v0.x *= 0.125f; v0.y *= 0.125f; v1.x *= 0.125f; v1.y *= 0.125f;
            v2.x *= 0.125f; v2.y *= 0.125f; v3.x *= 0.125f; v3.y *= 0.125f;
            qh[kc][0] = pack2(v0.x, v0.y); ql[kc][0] = resid2(v0.x, v0.y, qh[kc][0]);
            qh[kc][1] = pack2(v1.x, v1.y); ql[kc][1] = resid2(v1.x, v1.y, qh[kc][1]);
            qh[kc][2] = pack2(v2.x, v2.y); ql[kc][2] = resid2(v2.x, v2.y, qh[kc][2]);
            qh[kc][3] = pack2(v3.x, v3.y); ql[kc][3] = resid2(v3.x, v3.y, qh[kc][3]);
        }
    }

    float oacc[8][4];
#pragma unroll
    for (int n = 0; n < 8; ++n)
#pragma unroll
        for (int i = 0; i < 4; ++i) oacc[n][i] = 0.f;
    float m0 = -1e30f, m1 = -1e30f, l0 = 0.f, l1 = 0.f;

    for (int kt = 0; kt < SEQ / 64; ++kt) {
        __syncthreads();
        {   // K tile fill: 64 keys x 32 dpairs per plane (pure copy)
            size_t gk = (size_t)(kt * 64 + fk) * 32 + fkp;
            *(uint4*)&Khi[fk * KW + fkp]     = *(const uint4*)&khb[gk];
            *(uint4*)&Khi[fk * KW + fkp + 4] = *(const uint4*)&khb[gk + 4];
            *(uint4*)&Klo[fk * KW + fkp]     = *(const uint4*)&klb[gk];
            *(uint4*)&Klo[fk * KW + fkp + 4] = *(const uint4*)&klb[gk + 4];
            // V tile fill: 32 rowpairs x 64 dims per plane
            size_t gv = (size_t)(kt * 32 + fv) * 64 + fvd;
            *(uint4*)&Vhi[fv * VW + fvd]     = *(const uint4*)&vhb[gv];
            *(uint4*)&Vhi[fv * VW + fvd + 4] = *(const uint4*)&vhb[gv + 4];
            *(uint4*)&Vlo[fv * VW + fvd]     = *(const uint4*)&vlb[gv];
            *(uint4*)&Vlo[fv * VW + fvd + 4] = *(const uint4*)&vlb[gv + 4];
        }
        __syncthreads();

        // ---- S = Q K^T (16x64 per warp) ----
        float sacc[8][4];
#pragma unroll
        for (int n = 0; n < 8; ++n)
#pragma unroll
            for (int i = 0; i < 4; ++i) sacc[n][i] = 0.f;

#pragma unroll
        for (int kc = 0; kc < 4; ++kc) {
#pragma unroll
            for (int n = 0; n < 8; ++n) {
                const int wb = (n * 8 + gq) * KW + kc * 8 + tq;
                uint32_t bh0 = Khi[wb], bh1 = Khi[wb + 4];
                uint32_t bl0 = Klo[wb], bl1 = Klo[wb + 4];
                mma_bf16(sacc[n], qh[kc][0], qh[kc][1], qh[kc][2], qh[kc][3], bh0, bh1);
                mma_bf16(sacc[n], ql[kc][0], ql[kc][1], ql[kc][2], ql[kc][3], bh0, bh1);
                mma_bf16(sacc[n], qh[kc][0], qh[kc][1], qh[kc][2], qh[kc][3], bl0, bl1);
            }
        }

        // ---- online softmax (quad-reduce; row0 via c0/c1, row1 via c2/c3) ----
        float tm0 = -1e30f, tm1 = -1e30f;
#pragma unroll
        for (int n = 0; n < 8; ++n) {
            tm0 = fmaxf(tm0, fmaxf(sacc[n][0], sacc[n][1]));
            tm1 = fmaxf(tm1, fmaxf(sacc[n][2], sacc[n][3]));
        }
        tm0 = fmaxf(tm0, __shfl_xor_sync(0xffffffffu, tm0, 1));
        tm0 = fmaxf(tm0, __shfl_xor_sync(0xffffffffu, tm0, 2));
        tm1 = fmaxf(tm1, __shfl_xor_sync(0xffffffffu, tm1, 1));
        tm1 = fmaxf(tm1, __shfl_xor_sync(0xffffffffu, tm1, 2));
        float n0 = fmaxf(m0, tm0), n1 = fmaxf(m1, tm1);
        float sc0 = __expf(m0 - n0), sc1 = __expf(m1 - n1);
        m0 = n0; m1 = n1;
        float ps0 = 0.f, ps1 = 0.f;
#pragma unroll
        for (int n = 0; n < 8; ++n) {
            sacc[n][0] = __expf(sacc[n][0] - n0); ps0 += sacc[n][0];
            sacc[n][1] = __expf(sacc[n][1] - n0); ps0 += sacc[n][1];
            sacc[n][2] = __expf(sacc[n][2] - n1); ps1 += sacc[n][2];
            sacc[n][3] = __expf(sacc[n][3] - n1); ps1 += sacc[n][3];
        }
        ps0 += __shfl_xor_sync(0xffffffffu, ps0, 1);
        ps0 += __shfl_xor_sync(0xffffffffu, ps0, 2);
        ps1 += __shfl_xor_sync(0xffffffffu, ps1, 1);
        ps1 += __shfl_xor_sync(0xffffffffu, ps1, 2);
        l0 = l0 * sc0 + ps0;
        l1 = l1 * sc1 + ps1;
#pragma unroll
        for (int n = 0; n < 8; ++n) {
            oacc[n][0] *= sc0; oacc[n][1] *= sc0;
            oacc[n][2] *= sc1; oacc[n][3] *= sc1;
        }

        // ---- O += P V : accumulator pairs pack directly into A fragments ----
#pragma unroll
        for (int j = 0; j < 4; ++j) {
            uint32_t ph0 = pack2(sacc[2*j][0],   sacc[2*j][1]);
            uint32_t ph1 = pack2(sacc[2*j][2],   sacc[2*j][3]);
            uint32_t ph2 = pack2(sacc[2*j+1][0], sacc[2*j+1][1]);
            uint32_t ph3 = pack2(sacc[2*j+1][2], sacc[2*j+1][3]);
            uint32_t pl0 = resid2(sacc[2*j][0],   sacc[2*j][1],   ph0);
            uint32_t pl1 = resid2(sacc[2*j][2],   sacc[2*j][3],   ph1);
            uint32_t pl2 = resid2(sacc[2*j+1][0], sacc[2*j+1][1], ph2);
            uint32_t pl3 = resid2(sacc[2*j+1][2], sacc[2*j+1][3], ph3);
#pragma unroll
            for (int dt = 0; dt < 8; ++dt) {
                const int wb = (j * 8 + tq) * VW + dt * 8 + gq;
                uint32_t bh0 = Vhi[wb], bh1 = Vhi[wb + 4 * VW];
                uint32_t bl0 = Vlo[wb], bl1 = Vlo[wb + 4 * VW];
                mma_bf16(oacc[dt], ph0, ph1, ph2, ph3, bh0, bh1);
                mma_bf16(oacc[dt], pl0, pl1, pl2, pl3, bh0, bh1);
                mma_bf16(oacc[dt], ph0, ph1, ph2, ph3, bl0, bl1);
            }
        }
    }

    // ---- normalize + write ctx [tok, h*64+d] (fp32, round-4 verbatim) ----
    float inv0 = 1.f / l0, inv1 = 1.f / l1;
    float* cp = Ctx + (size_t)(b * SEQ) * EMB + h * KDIM;
#pragma unroll
    for (int dt = 0; dt < 8; ++dt) {
        *(float2*)&cp[(size_t)row0 * EMB + dt * 8 + 2 * tq] =
            make_float2(oacc[dt][0] * inv0, oacc[dt][1] * inv0);
        *(float2*)&cp[(size_t)row1 * EMB + dt * 8 + 2 * tq] =
            make_float2(oacc[dt][2] * inv1, oacc[dt][3] * inv1);
    }
}

// ---------------------------------------------------------------------------
extern "C" void kernel_launch(void* const* d_in, const int* in_sizes, int n_in,
                              void* d_out, int out_size)
{
    const float* x   = (const float*)d_in[0];   // [4,2048,512]
    const float* key = (const float*)d_in[1];   // [4,8,2048,64]
    const float* val = (const float*)d_in[2];   // [4,8,2048,64]
    const float* wq  = (const float*)d_in[3];   // [512,512]
    const float* wo  = (const float*)d_in[4];   // [512,512]
    float* out = (float*)d_out;                 // [4,2048,512]

    float *qptr, *cptr;
    uint32_t *kph, *kpl, *vph, *vpl;
    cudaGetSymbolAddress((void**)&qptr, g_q);
    cudaGetSymbolAddress((void**)&cptr, g_ctx);
    cudaGetSymbolAddress((void**)&kph, g_kp_hi); cudaGetSymbolAddress((void**)&kpl, g_kp_lo);
    cudaGetSymbolAddress((void**)&vph, g_vp_hi); cudaGetSymbolAddress((void**)&vpl, g_vp_lo);

    // ---- pre-pack K (contiguous dpairs) and V (rowpairs) ----
    const int n4k  = BH * SEQ * KDIM / 4;   // 1,048,576 float4s
    const int np2v = BH * SEQ * KDIM / 4;   // 1,048,576 word-pairs
    pack_cont<<<(n4k  + 255) / 256, 256>>>(key, kph, kpl, n4k);
    pack_rows<<<(np2v + 255) / 256, 256>>>(val, vph, vpl, np2v, KDIM);

    // 1) Q = x @ Wq  (round-13 GEMM, single-wave 128x128)
    gemm_bf16s<<<dim3(EMB / 128, TOKENS / 128), 256>>>(x, wq, qptr, TOKENS, EMB, EMB);
    // 2) attention (pre-packed K/V; round-4 compute core)
    attn_mma<<<dim3(SEQ / 128, BH), 256>>>(qptr, kph, kpl, vph, vpl, cptr);
    // 3) out = ctx @ Wo
    gemm_bf16s<<<dim3(EMB / 128, TOKENS / 128), 256>>>(cptr, wo, out, TOKENS, EMB, EMB);
}

// round 16
// speedup vs baseline: 1.3304x; 1.0720x over previous
#include <cuda_runtime.h>
#include <cstdint>
#include <cstddef>

// Problem constants
#define BATCH 4
#define SEQ   2048
#define EMB   512
#define HEADS 8
#define KDIM  64
#define TOKENS (BATCH * SEQ)          // 8192
#define BH    (BATCH * HEADS)         // 32

// Scratch (allocation-free rule: __device__ globals)
__device__ float    g_q  [TOKENS * EMB];   // Q = x @ Wq, [tok, h*64+d]
__device__ float    g_ctx[TOKENS * EMB];   // context,    [tok, h*64+d]
__device__ uint32_t g_kp_hi[BH * SEQ * 32], g_kp_lo[BH * SEQ * 32];   // K dpairs
__device__ uint32_t g_vp_hi[BH * 1024 * 64], g_vp_lo[BH * 1024 * 64]; // V rowpairs

// ---------------------------------------------------------------------------
// helpers
// ---------------------------------------------------------------------------
__device__ __forceinline__ uint32_t pack2(float lo, float hi) {
    uint32_t r;
    asm("cvt.rn.bf16x2.f32 %0, %1, %2;" : "=r"(r) : "f"(hi), "f"(lo));
    return r;
}
__device__ __forceinline__ float unlo(uint32_t p) { return __uint_as_float(p << 16); }
__device__ __forceinline__ float unhi(uint32_t p) { return __uint_as_float(p & 0xffff0000u); }
__device__ __forceinline__ uint32_t resid2(float lo, float hi, uint32_t h) {
    return pack2(lo - unlo(h), hi - unhi(h));
}
__device__ __forceinline__ void mma_bf16(float* c,
                                         uint32_t a0, uint32_t a1, uint32_t a2, uint32_t a3,
                                         uint32_t b0, uint32_t b1)
{
    asm volatile(
        "mma.sync.aligned.m16n8k16.row.col.f32.bf16.bf16.f32 "
        "{%0,%1,%2,%3}, {%4,%5,%6,%7}, {%8,%9}, {%0,%1,%2,%3};\n"
        : "+f"(c[0]), "+f"(c[1]), "+f"(c[2]), "+f"(c[3])
        : "r"(a0), "r"(a1), "r"(a2), "r"(a3), "r"(b0), "r"(b1));
}

// smem row widths (uint32 words) — conflict-free fragment LDS (r4/r13 proven)
#define KW  36   // K/A-style: [row][pair], 32 pairs + 4 pad
#define VW  72   // V-style: [rowpair][col], 64 cols + 8 pad
#define VW2 136  // B-style (128-wide): [rowpair][col], 128 cols + 8 pad
#define AW  20   // A packed row width

// ===========================================================================
// Pre-pack kernels (one-time, memory-bound).
// ===========================================================================
__global__ void pack_cont(const float* __restrict__ src,
                          uint32_t* __restrict__ hi, uint32_t* __restrict__ lo, int n4)
{
    int i = blockIdx.x * blockDim.x + threadIdx.x;
    if (i >= n4) return;
    float4 a = ((const float4*)src)[i];
    uint32_t h0 = pack2(a.x, a.y), h1 = pack2(a.z, a.w);
    ((uint2*)hi)[i] = make_uint2(h0, h1);
    ((uint2*)lo)[i] = make_uint2(resid2(a.x, a.y, h0), resid2(a.z, a.w, h1));
}
__global__ void pack_rows(const float* __restrict__ src,
                          uint32_t* __restrict__ hi, uint32_t* __restrict__ lo,
                          int npairs2, int W)
{
    int j = blockIdx.x * blockDim.x + threadIdx.x;
    if (j >= npairs2) return;
    int i2 = 2 * j;
    int rp = i2 / W, d = i2 % W;
    float2 r0 = *(const float2*)&src[(size_t)(2 * rp) * W + d];
    float2 r1 = *(const float2*)&src[(size_t)(2 * rp + 1) * W + d];
    uint32_t h0 = pack2(r0.x, r1.x), h1 = pack2(r0.y, r1.y);
    *(uint2*)&hi[i2] = make_uint2(h0, h1);
    *(uint2*)&lo[i2] = make_uint2(resid2(r0.x, r1.x, h0), resid2(r0.y, r1.y, h1));
}

// ===========================================================================
// Split-bf16 GEMM (round-13 VERBATIM): C = A @ B, 128x128 tile, BK=32,
// single-wave grid (256 CTAs at 2 CTAs/SM).
// ===========================================================================
__global__ __launch_bounds__(256) void gemm_bf16s(
    const float* __restrict__ A, const float* __restrict__ Bm,
    float* __restrict__ C, int M, int N, int K)
{
    __shared__ uint32_t Ahi[128 * AW], Alo[128 * AW];
    __shared__ uint32_t Bhi[16 * VW2], Blo[16 * VW2];

    const int tid  = threadIdx.x;
    const int warp = tid >> 5, lane = tid & 31;
    const int g = lane >> 2, t = lane & 3;
    const int bn = blockIdx.x << 7;
    const int bm = blockIdx.y << 7;
    const int wm = warp << 4;

    const int cr = tid >> 1, c16 = (tid & 1) << 4;
    const int nn = (tid & 63) << 1, rr = (tid >> 6) << 3;

    float acc[16][4];
#pragma unroll
    for (int n = 0; n < 16; ++n)
#pragma unroll
        for (int i = 0; i < 4; ++i) acc[n][i] = 0.f;

    for (int kt = 0; kt < K; kt += 32) {
        __syncthreads();
        {
            const float* ar = &A[(size_t)(bm + cr) * K + kt + c16];
#pragma unroll
            for (int i = 0; i < 4; ++i) {
                float4 a = *(const float4*)&ar[4 * i];
                uint32_t h0 = pack2(a.x, a.y), h1 = pack2(a.z, a.w);
                int w = cr * AW + (c16 >> 1) + 2 * i;
                *(uint2*)&Ahi[w] = make_uint2(h0, h1);
                *(uint2*)&Alo[w] = make_uint2(resid2(a.x, a.y, h0), resid2(a.z, a.w, h1));
            }
#pragma unroll
            for (int i = 0; i < 4; ++i) {
                int r0 = rr + 2 * i;
                float2 p = *(const float2*)&Bm[(size_t)(kt + r0)     * N + bn + nn];
                float2 q = *(const float2*)&Bm[(size_t)(kt + r0 + 1) * N + bn + nn];
                uint32_t h0 = pack2(p.x, q.x), h1 = pack2(p.y, q.y);
                int w = (r0 >> 1) * VW2 + nn;
                *(uint2*)&Bhi[w] = make_uint2(h0, h1);
                *(uint2*)&Blo[w] = make_uint2(resid2(p.x, q.x, h0), resid2(p.y, q.y, h1));
            }
        }
        __syncthreads();

#pragma unroll
        for (int kc = 0; kc < 2; ++kc) {
            const int wa = (wm + g) * AW + kc * 8 + t;
            uint32_t ah0 = Ahi[wa],     ah1 = Ahi[wa + 8 * AW];
            uint32_t ah2 = Ahi[wa + 4], ah3 = Ahi[wa + 8 * AW + 4];
            uint32_t al0 = Alo[wa],     al1 = Alo[wa + 8 * AW];
            uint32_t al2 = Alo[wa + 4], al3 = Alo[wa + 8 * AW + 4];
#pragma unroll
            for (int n = 0; n < 16; ++n) {
                const int wb = (kc * 8 + t) * VW2 + n * 8 + g;
                uint32_t bh0 = Bhi[wb], bh1 = Bhi[wb + 4 * VW2];
                uint32_t bl0 = Blo[wb], bl1 = Blo[wb + 4 * VW2];
                mma_bf16(acc[n], ah0, ah1, ah2, ah3, bh0, bh1);
                mma_bf16(acc[n], al0, al1, al2, al3, bh0, bh1);
                mma_bf16(acc[n], ah0, ah1, ah2, ah3, bl0, bl1);
            }
        }
    }

    const int row0 = bm + wm + g, row1 = row0 + 8;
#pragma unroll
    for (int n = 0; n < 16; ++n) {
        *(float2*)&C[(size_t)row0 * N + bn + n * 8 + 2 * t] = make_float2(acc[n][0], acc[n][1]);
        *(float2*)&C[(size_t)row1 * N + bn + n * 8 + 2 * t] = make_float2(acc[n][2], acc[n][3]);
    }
}

// ===========================================================================
// Flash attention (round-15 core + __launch_bounds__(256,2)): force regs
// <=128 so 2 CTAs/SM are resident — wave structure 3.46 -> 1.73 waves and
// cross-CTA overlap of fill/barrier phases. Compute identical to round 15.
// ===========================================================================
__global__ __launch_bounds__(256, 2) void attn_mma(
    const float* __restrict__ Q,          // [tok, 512] fp32 from g_q
    const uint32_t* __restrict__ Khig, const uint32_t* __restrict__ Klog,
    const uint32_t* __restrict__ Vhig, const uint32_t* __restrict__ Vlog,
    float* __restrict__ Ctx)              // [tok, 512] fp32
{
    __shared__ uint32_t Khi[64 * KW], Klo[64 * KW];   // [key][dpair]
    __shared__ uint32_t Vhi[32 * VW], Vlo[32 * VW];   // [rowpair][d]

    const int tid  = threadIdx.x;
    const int warp = tid >> 5, lane = tid & 31;
    const int gq = lane >> 2, tq = lane & 3;
    const int bh = blockIdx.y;
    const int b  = bh >> 3, h = bh & 7;
    const int q0 = blockIdx.x << 7;
    const int row0 = q0 + warp * 16 + gq;
    const int row1 = row0 + 8;

    const uint32_t* khb = Khig + (size_t)bh * SEQ * 32;
    const uint32_t* klb = Klog + (size_t)bh * SEQ * 32;
    const uint32_t* vhb = Vhig + (size_t)bh * 1024 * 64;
    const uint32_t* vlb = Vlog + (size_t)bh * 1024 * 64;

    // fill mappings (pure copy)
    const int fk = tid >> 2, fkp = (tid & 3) << 3;    // K: key, dpair base
    const int fv = tid >> 3, fvd = (tid & 7) << 3;    // V: rowpair, dim base

    // ---- Q fragments (bf16 hi/lo), pre-scaled by 1/sqrt(64) ----
    uint32_t qh[4][4], ql[4][4];
    {
        const float* qp = Q + (size_t)(b * SEQ) * EMB + h * KDIM;
#pragma unroll
        for (int kc = 0; kc < 4; ++kc) {
            float2 v0 = *(const float2*)&qp[(size_t)row0 * EMB + kc * 16 + 2 * tq];
            float2 v1 = *(const float2*)&qp[(size_t)row1 * EMB + kc * 16 + 2 * tq];
            float2 v2 = *(const float2*)&qp[(size_t)row0 * EMB + kc * 16 + 2 * tq + 8];
            float2 v3 = *(const float2*)&qp[(size_t)row1 * EMB + kc * 16 + 2 * tq + 8];
            v0.x *= 0.125f; v0.y *= 0.125f; v1.x *= 0.125f; v1.y *= 0.125f;
            v2.x *= 0.125f; v2.y *= 0.125f; v3.x *= 0.125f; v3.y *= 0.125f;
            qh[kc][0] = pack2(v0.x, v0.y); ql[kc][0] = resid2(v0.x, v0.y, qh[kc][0]);
            qh[kc][1] = pack2(v1.x, v1.y); ql[kc][1] = resid2(v1.x, v1.y, qh[kc][1]);
            qh[kc][2] = pack2(v2.x, v2.y); ql[kc][2] = resid2(v2.x, v2.y, qh[kc][2]);
            qh[kc][3] = pack2(v3.x, v3.y); ql[kc][3] = resid2(v3.x, v3.y, qh[kc][3]);
        }
    }

    float oacc[8][4];
#pragma unroll
    for (int n = 0; n < 8; ++n)
#pragma unroll
        for (int i = 0; i < 4; ++i) oacc[n][i] = 0.f;
    float m0 = -1e30f, m1 = -1e30f, l0 = 0.f, l1 = 0.f;

    for (int kt = 0; kt < SEQ / 64; ++kt) {
        __syncthreads();
        {   // K tile fill: 64 keys x 32 dpairs per plane (pure copy)
            size_t gk = (size_t)(kt * 64 + fk) * 32 + fkp;
            *(uint4*)&Khi[fk * KW + fkp]     = *(const uint4*)&khb[gk];
            *(uint4*)&Khi[fk * KW + fkp + 4] = *(const uint4*)&khb[gk + 4];
            *(uint4*)&Klo[fk * KW + fkp]     = *(const uint4*)&klb[gk];
            *(uint4*)&Klo[fk * KW + fkp + 4] = *(const uint4*)&klb[gk + 4];
            // V tile fill: 32 rowpairs x 64 dims per plane
            size_t gv = (size_t)(kt * 32 + fv) * 64 + fvd;
            *(uint4*)&Vhi[fv * VW + fvd]     = *(const uint4*)&vhb[gv];
            *(uint4*)&Vhi[fv * VW + fvd + 4] = *(const uint4*)&vhb[gv + 4];
            *(uint4*)&Vlo[fv * VW + fvd]     = *(const uint4*)&vlb[gv];
            *(uint4*)&Vlo[fv * VW + fvd + 4] = *(const uint4*)&vlb[gv + 4];
        }
        __syncthreads();

        // ---- S = Q K^T (16x64 per warp) ----
        float sacc[8][4];
#pragma unroll
        for (int n = 0; n < 8; ++n)
#pragma unroll
            for (int i = 0; i < 4; ++i) sacc[n][i] = 0.f;

#pragma unroll
        for (int kc = 0; kc < 4; ++kc) {
#pragma unroll
            for (int n = 0; n < 8; ++n) {
                const int wb = (n * 8 + gq) * KW + kc * 8 + tq;
                uint32_t bh0 = Khi[wb], bh1 = Khi[wb + 4];
                uint32_t bl0 = Klo[wb], bl1 = Klo[wb + 4];
                mma_bf16(sacc[n], qh[kc][0], qh[kc][1], qh[kc][2], qh[kc][3], bh0, bh1);
                mma_bf16(sacc[n], ql[kc][0], ql[kc][1], ql[kc][2], ql[kc][3], bh0, bh1);
                mma_bf16(sacc[n], qh[kc][0], qh[kc][1], qh[kc][2], qh[kc][3], bl0, bl1);
            }
        }

        // ---- online softmax (quad-reduce; row0 via c0/c1, row1 via c2/c3) ----
        float tm0 = -1e30f, tm1 = -1e30f;
#pragma unroll
        for (int n = 0; n < 8; ++n) {
            tm0 = fmaxf(tm0, fmaxf(sacc[n][0], sacc[n][1]));
            tm1 = fmaxf(tm1, fmaxf(sacc[n][2], sacc[n][3]));
        }
        tm0 = fmaxf(tm0, __shfl_xor_sync(0xffffffffu, tm0, 1));
        tm0 = fmaxf(tm0, __shfl_xor_sync(0xffffffffu, tm0, 2));
        tm1 = fmaxf(tm1, __shfl_xor_sync(0xffffffffu, tm1, 1));
        tm1 = fmaxf(tm1, __shfl_xor_sync(0xffffffffu, tm1, 2));
        float n0 = fmaxf(m0, tm0), n1 = fmaxf(m1, tm1);
        float sc0 = __expf(m0 - n0), sc1 = __expf(m1 - n1);
        m0 = n0; m1 = n1;
        float ps0 = 0.f, ps1 = 0.f;
#pragma unroll
        for (int n = 0; n < 8; ++n) {
            sacc[n][0] = __expf(sacc[n][0] - n0); ps0 += sacc[n][0];
            sacc[n][1] = __expf(sacc[n][1] - n0); ps0 += sacc[n][1];
            sacc[n][2] = __expf(sacc[n][2] - n1); ps1 += sacc[n][2];
            sacc[n][3] = __expf(sacc[n][3] - n1); ps1 += sacc[n][3];
        }
        ps0 += __shfl_xor_sync(0xffffffffu, ps0, 1);
        ps0 += __shfl_xor_sync(0xffffffffu, ps0, 2);
        ps1 += __shfl_xor_sync(0xffffffffu, ps1, 1);
        ps1 += __shfl_xor_sync(0xffffffffu, ps1, 2);
        l0 = l0 * sc0 + ps0;
        l1 = l1 * sc1 + ps1;
#pragma unroll
        for (int n = 0; n < 8; ++n) {
            oacc[n][0] *= sc0; oacc[n][1] *= sc0;
            oacc[n][2] *= sc1; oacc[n][3] *= sc1;
        }

        // ---- O += P V : accumulator pairs pack directly into A fragments ----
#pragma unroll
        for (int j = 0; j < 4; ++j) {
            uint32_t ph0 = pack2(sacc[2*j][0],   sacc[2*j][1]);
            uint32_t ph1 = pack2(sacc[2*j][2],   sacc[2*j][3]);
            uint32_t ph2 = pack2(sacc[2*j+1][0], sacc[2*j+1][1]);
            uint32_t ph3 = pack2(sacc[2*j+1][2], sacc[2*j+1][3]);
            uint32_t pl0 = resid2(sacc[2*j][0],   sacc[2*j][1],   ph0);
            uint32_t pl1 = resid2(sacc[2*j][2],   sacc[2*j][3],   ph1);
            uint32_t pl2 = resid2(sacc[2*j+1][0], sacc[2*j+1][1], ph2);
            uint32_t pl3 = resid2(sacc[2*j+1][2], sacc[2*j+1][3], ph3);
#pragma unroll
            for (int dt = 0; dt < 8; ++dt) {
                const int wb = (j * 8 + tq) * VW + dt * 8 + gq;
                uint32_t bh0 = Vhi[wb], bh1 = Vhi[wb + 4 * VW];
                uint32_t bl0 = Vlo[wb], bl1 = Vlo[wb + 4 * VW];
                mma_bf16(oacc[dt], ph0, ph1, ph2, ph3, bh0, bh1);
                mma_bf16(oacc[dt], pl0, pl1, pl2, pl3, bh0, bh1);
                mma_bf16(oacc[dt], ph0, ph1, ph2, ph3, bl0, bl1);
            }
        }
    }

    // ---- normalize + write ctx [tok, h*64+d] ----
    float inv0 = 1.f / l0, inv1 = 1.f / l1;
    float* cp = Ctx + (size_t)(b * SEQ) * EMB + h * KDIM;
#pragma unroll
    for (int dt = 0; dt < 8; ++dt) {
        *(float2*)&cp[(size_t)row0 * EMB + dt * 8 + 2 * tq] =
            make_float2(oacc[dt][0] * inv0, oacc[dt][1] * inv0);
        *(float2*)&cp[(size_t)row1 * EMB + dt * 8 + 2 * tq] =
            make_float2(oacc[dt][2] * inv1, oacc[dt][3] * inv1);
    }
}

// ---------------------------------------------------------------------------
extern "C" void kernel_launch(void* const* d_in, const int* in_sizes, int n_in,
                              void* d_out, int out_size)
{
    const float* x   = (const float*)d_in[0];   // [4,2048,512]
    const float* key = (const float*)d_in[1];   // [4,8,2048,64]
    const float* val = (const float*)d_in[2];   // [4,8,2048,64]
    const float* wq  = (const float*)d_in[3];   // [512,512]
    const float* wo  = (const float*)d_in[4];   // [512,512]
    float* out = (float*)d_out;                 // [4,2048,512]

    float *qptr, *cptr;
    uint32_t *kph, *kpl, *vph, *vpl;
    cudaGetSymbolAddress((void**)&qptr, g_q);
    cudaGetSymbolAddress((void**)&cptr, g_ctx);
    cudaGetSymbolAddress((void**)&kph, g_kp_hi); cudaGetSymbolAddress((void**)&kpl, g_kp_lo);
    cudaGetSymbolAddress((void**)&vph, g_vp_hi); cudaGetSymbolAddress((void**)&vpl, g_vp_lo);

    // ---- pre-pack K (contiguous dpairs) and V (rowpairs) ----
    const int n4k  = BH * SEQ * KDIM / 4;   // 1,048,576 float4s
    const int np2v = BH * SEQ * KDIM / 4;   // 1,048,576 word-pairs
    pack_cont<<<(n4k  + 255) / 256, 256>>>(key, kph, kpl, n4k);
    pack_rows<<<(np2v + 255) / 256, 256>>>(val, vph, vpl, np2v, KDIM);

    // 1) Q = x @ Wq  (round-13 GEMM, single-wave 128x128)
    gemm_bf16s<<<dim3(EMB / 128, TOKENS / 128), 256>>>(x, wq, qptr, TOKENS, EMB, EMB);
    // 2) attention (pre-packed K/V; 2 CTAs/SM)
    attn_mma<<<dim3(SEQ / 128, BH), 256>>>(qptr, kph, kpl, vph, vpl, cptr);
    // 3) out = ctx @ Wo
    gemm_bf16s<<<dim3(EMB / 128, TOKENS / 128), 256>>>(cptr, wo, out, TOKENS, EMB, EMB);
}